// round 4
// baseline (speedup 1.0000x reference)
#include <cuda_runtime.h>
#include <cstdint>
#include <cstddef>

// ---------------------------------------------------------------------------
// Problem constants
// ---------------------------------------------------------------------------
#define Nn 2048
#define Ee 32768
#define Tt 12
#define XD 128
#define HD 256
#define ZD 32

constexpr size_t SZ_HD  = (size_t)Nn * HD;      // 524288
constexpr size_t SZ_2HD = (size_t)Nn * 2 * HD;  // 1048576
constexpr size_t SZ_ZD  = (size_t)Nn * ZD;      // 65536

// ---------------------------------------------------------------------------
// Scratch (single __device__ array; no runtime allocation)
// ---------------------------------------------------------------------------
constexpr size_t O_CAT   = 0;                    // [N,512]  (phi_x | h1)
constexpr size_t O_CATP  = O_CAT   + SZ_2HD;     // gin(cat)
constexpr size_t O_ENC_S = O_CATP  + SZ_2HD;
constexpr size_t O_ENC_D = O_ENC_S + SZ_HD;
constexpr size_t O_XW_S  = O_ENC_D + SZ_HD;      // enc_s @ mean_w
constexpr size_t O_XW_D  = O_XW_S  + SZ_ZD;
constexpr size_t O_MEAN_S= O_XW_D  + SZ_ZD;
constexpr size_t O_MEAN_D= O_MEAN_S+ SZ_ZD;
constexpr size_t O_STMP_S= O_MEAN_D+ SZ_ZD;      // enc_s @ std_w
constexpr size_t O_STMP_D= O_STMP_S+ SZ_ZD;
constexpr size_t O_STD_S = O_STMP_D+ SZ_ZD;
constexpr size_t O_STD_D = O_STD_S + SZ_ZD;
constexpr size_t O_PRI_S = O_STD_D + SZ_ZD;      // [N,256]
constexpr size_t O_PRI_D = O_PRI_S + SZ_HD;
constexpr size_t O_PM_S  = O_PRI_D + SZ_HD;
constexpr size_t O_PS_S  = O_PM_S  + SZ_ZD;
constexpr size_t O_PM_D  = O_PS_S  + SZ_ZD;
constexpr size_t O_PS_D  = O_PM_D  + SZ_ZD;
constexpr size_t O_Z_S   = O_PS_D  + SZ_ZD;
constexpr size_t O_Z_D   = O_Z_S   + SZ_ZD;
constexpr size_t O_ZCAT  = O_Z_D   + SZ_ZD;      // [N,64]
constexpr size_t O_GIN   = O_ZCAT  + (size_t)Nn * 2 * ZD;  // [N,512] (phi_x|phi_z)
constexpr size_t O_GPRE  = O_GIN   + SZ_2HD;     // gin(g_in) [N,512]
constexpr size_t O_HPRE  = O_GPRE  + SZ_2HD;     // gin(h[i]) [N,256]
constexpr size_t O_XPRE1 = O_HPRE  + SZ_HD;      // gin(new_h0) [N,256]
constexpr size_t O_TZ    = O_XPRE1 + SZ_HD;
constexpr size_t O_TR    = O_TZ    + SZ_HD;
constexpr size_t O_TH    = O_TR    + SZ_HD;
constexpr size_t O_RH    = O_TH    + SZ_HD;
constexpr size_t O_RHP   = O_RH    + SZ_HD;
constexpr size_t O_H     = O_RHP   + SZ_HD;      // 2 dbl-buffers x NL layers
constexpr size_t TOTAL_F = O_H + 4 * SZ_HD;

__device__ __align__(256) float g_f[TOTAL_F];
__device__ int    d_deg[Nn];
__device__ int    d_cursor[Nn];
__device__ int    d_rowptr[Nn + 1];
__device__ int    d_csrsrc[Ee];
__device__ float  d_degf[Nn];
__device__ float  d_dinv[Nn];
__device__ double d_acc[6];  // 0:ssum 1:S1 2:S2 3:kld-step 4:kld-total 5:nll-total

// ---------------------------------------------------------------------------
// Activations / reductions
// ---------------------------------------------------------------------------
template<int ACT>
__device__ __forceinline__ float activate(float v) {
    if (ACT == 1) return fmaxf(v, 0.f);
    if (ACT == 2) return 1.f / (1.f + expf(-v));
    if (ACT == 3) return tanhf(v);
    if (ACT == 4) return fmaxf(v, 0.f) + log1pf(expf(-fabsf(v)));  // softplus
    return v;
}

__device__ __forceinline__ void block_add(double* target, float v) {
    #pragma unroll
    for (int o = 16; o; o >>= 1) v += __shfl_down_sync(0xffffffffu, v, o);
    __shared__ float wsum[32];
    int lane = threadIdx.x & 31, wid = threadIdx.x >> 5;
    if (lane == 0) wsum[wid] = v;
    __syncthreads();
    if (threadIdx.x == 0) {
        float s = 0.f;
        int nw = (blockDim.x + 31) >> 5;
        for (int i = 0; i < nw; i++) s += wsum[i];
        atomicAdd(target, (double)s);
    }
    __syncthreads();
}

// ---------------------------------------------------------------------------
// SGEMM: C = act( A[M,K]@B[K,Ncol] (+ C if BETA) (+ bias) )
// BM=64, BK=16, 4x4 micro-tile. BN=64 -> 256 thr; BN=32 -> 128 thr.
// ---------------------------------------------------------------------------
template<int BN, int ACT, int BETA>
__global__ void __launch_bounds__(16 * (BN / 4) * 4)
sgemm(const float* __restrict__ A, const float* __restrict__ B,
      const float* __restrict__ bias, float* __restrict__ C,
      int K, int lda, int ldb, int ldc)
{
    constexpr int BM = 64, BK = 16, TM = 4, TN = 4;
    constexpr int TX = BN / TN, TY = BM / TM;
    constexpr int THREADS = TX * TY;
    constexpr int AITER = (BM * BK) / THREADS;
    constexpr int BITER = (BK * BN) / THREADS;

    __shared__ float As[BK][BM + 1];
    __shared__ float Bs[BK][BN + 1];

    const int tid = threadIdx.x;
    const int bm = blockIdx.y * BM, bn = blockIdx.x * BN;
    const int tx = tid % TX, ty = tid / TX;

    float acc[TM][TN];
    #pragma unroll
    for (int i = 0; i < TM; i++)
        #pragma unroll
        for (int j = 0; j < TN; j++) acc[i][j] = 0.f;

    for (int k0 = 0; k0 < K; k0 += BK) {
        #pragma unroll
        for (int it = 0; it < AITER; it++) {
            int i = tid + it * THREADS;
            int m = i / BK, k = i % BK;
            As[k][m] = A[(size_t)(bm + m) * lda + k0 + k];
        }
        #pragma unroll
        for (int it = 0; it < BITER; it++) {
            int i = tid + it * THREADS;
            int k = i / BN, n = i % BN;
            Bs[k][n] = B[(size_t)(k0 + k) * ldb + bn + n];
        }
        __syncthreads();
        #pragma unroll
        for (int k = 0; k < BK; k++) {
            float a[TM], b[TN];
            #pragma unroll
            for (int i = 0; i < TM; i++) a[i] = As[k][ty * TM + i];
            #pragma unroll
            for (int j = 0; j < TN; j++) b[j] = Bs[k][tx * TN + j];
            #pragma unroll
            for (int i = 0; i < TM; i++)
                #pragma unroll
                for (int j = 0; j < TN; j++) acc[i][j] += a[i] * b[j];
        }
        __syncthreads();
    }

    #pragma unroll
    for (int i = 0; i < TM; i++) {
        int m = bm + ty * TM + i;
        #pragma unroll
        for (int j = 0; j < TN; j++) {
            int n = bn + tx * TN + j;
            float v = acc[i][j];
            if (BETA) v += C[(size_t)m * ldc + n];
            if (bias) v += bias[n];
            C[(size_t)m * ldc + n] = activate<ACT>(v);
        }
    }
}

// ---------------------------------------------------------------------------
// CSR build
// ---------------------------------------------------------------------------
__global__ void zero_csr_kernel() {
    int i = blockIdx.x * blockDim.x + threadIdx.x;
    if (i < Nn) { d_deg[i] = 0; d_cursor[i] = 0; }
}
__global__ void hist_kernel(const int* __restrict__ dst) {
    int i = blockIdx.x * blockDim.x + threadIdx.x;
    if (i < Ee) atomicAdd(&d_deg[dst[i]], 1);
}
__global__ void scan_kernel() {
    __shared__ int s0[2048], s1[2048];
    int t = threadIdx.x;  // 1024 threads
    s0[t] = d_deg[t]; s0[t + 1024] = d_deg[t + 1024];
    __syncthreads();
    int* cur = s0; int* nxt = s1;
    for (int off = 1; off < 2048; off <<= 1) {
        int i0 = t, i1 = t + 1024;
        nxt[i0] = cur[i0] + (i0 >= off ? cur[i0 - off] : 0);
        nxt[i1] = cur[i1] + (i1 >= off ? cur[i1 - off] : 0);
        __syncthreads();
        int* tmp = cur; cur = nxt; nxt = tmp;
    }
    d_rowptr[t + 1]    = cur[t];
    d_rowptr[t + 1025] = cur[t + 1024];
    if (t == 0) d_rowptr[0] = 0;
    float f0 = (float)(d_deg[t] + 1);
    float f1 = (float)(d_deg[t + 1024] + 1);
    d_degf[t] = f0;          d_dinv[t] = rsqrtf(f0);
    d_degf[t + 1024] = f1;   d_dinv[t + 1024] = rsqrtf(f1);
}
__global__ void fill_kernel(const int* __restrict__ src, const int* __restrict__ dst) {
    int i = blockIdx.x * blockDim.x + threadIdx.x;
    if (i < Ee) {
        int d = dst[i];
        int pos = atomicAdd(&d_cursor[d], 1);
        d_csrsrc[d_rowptr[d] + pos] = src[i];
    }
}

// ---------------------------------------------------------------------------
// Graph gathers
// ---------------------------------------------------------------------------
// out[n] = x[n] + sum_{e: dst=n} x[src_e]; blockDim = 128 = D4*npb
__global__ void gin_kernel(const float4* __restrict__ x, float4* __restrict__ out,
                           int D4, int npb)
{
    int lane = threadIdx.x % D4;
    int n = blockIdx.x * npb + threadIdx.x / D4;
    int beg = d_rowptr[n], end = d_rowptr[n + 1];
    float4 acc = x[(size_t)n * D4 + lane];
    for (int e = beg; e < end; e++) {
        float4 v = x[(size_t)d_csrsrc[e] * D4 + lane];
        acc.x += v.x; acc.y += v.y; acc.z += v.z; acc.w += v.w;
    }
    out[(size_t)n * D4 + lane] = acc;
}

// GCN (32-wide): out = dinv[n]*sum(dinv[s]*xw[s]) + xw[n]/deg[n] + b
__global__ void gcn_kernel(const float4* __restrict__ xw, float4* __restrict__ out,
                           const float4* __restrict__ bias)
{
    int lane = threadIdx.x & 7;                 // 8 float4 = 32 floats
    int n = blockIdx.x * 16 + (threadIdx.x >> 3);
    int beg = d_rowptr[n], end = d_rowptr[n + 1];
    float4 acc = make_float4(0.f, 0.f, 0.f, 0.f);
    for (int e = beg; e < end; e++) {
        int s = d_csrsrc[e];
        float w = d_dinv[s];
        float4 v = xw[(size_t)s * 8 + lane];
        acc.x += w * v.x; acc.y += w * v.y; acc.z += w * v.z; acc.w += w * v.w;
    }
    float dn = d_dinv[n], id = 1.f / d_degf[n];
    float4 xn = xw[(size_t)n * 8 + lane];
    float4 b = bias[lane];
    out[(size_t)n * 8 + lane] = make_float4(
        dn * acc.x + id * xn.x + b.x, dn * acc.y + id * xn.y + b.y,
        dn * acc.z + id * xn.z + b.z, dn * acc.w + id * xn.w + b.w);
}

// std path (32-wide): out = softplus( gin(tmp) + b )
__global__ void stdsp_kernel(const float4* __restrict__ tmp, float4* __restrict__ out,
                             const float4* __restrict__ bias)
{
    int lane = threadIdx.x & 7;
    int n = blockIdx.x * 16 + (threadIdx.x >> 3);
    int beg = d_rowptr[n], end = d_rowptr[n + 1];
    float4 acc = tmp[(size_t)n * 8 + lane];
    for (int e = beg; e < end; e++) {
        float4 v = tmp[(size_t)d_csrsrc[e] * 8 + lane];
        acc.x += v.x; acc.y += v.y; acc.z += v.z; acc.w += v.w;
    }
    float4 b = bias[lane];
    out[(size_t)n * 8 + lane] = make_float4(
        activate<4>(acc.x + b.x), activate<4>(acc.y + b.y),
        activate<4>(acc.z + b.z), activate<4>(acc.w + b.w));
}

// ---------------------------------------------------------------------------
// Elementwise
// ---------------------------------------------------------------------------
__global__ void copy2d_kernel(const float* __restrict__ src, int lds,
                              float* __restrict__ dst, int ldd, int D)
{
    int i = blockIdx.x * blockDim.x + threadIdx.x;
    if (i < Nn * D) {
        int n = i / D, j = i % D;
        dst[(size_t)n * ldd + j] = src[(size_t)n * lds + j];
    }
}

__global__ void z_kernel(const float* __restrict__ ms, const float* __restrict__ ss,
                         const float* __restrict__ es, const float* __restrict__ md,
                         const float* __restrict__ sd, const float* __restrict__ ed,
                         float* __restrict__ zs, float* __restrict__ zd,
                         float* __restrict__ zcat)
{
    int i = blockIdx.x * blockDim.x + threadIdx.x;
    if (i < Nn * ZD) {
        int n = i >> 5, j = i & 31;
        float a = ms[i] + ss[i] * es[i];
        float b = md[i] + sd[i] * ed[i];
        zs[i] = a; zd[i] = b;
        zcat[(size_t)n * 64 + j] = a;
        zcat[(size_t)n * 64 + 32 + j] = b;
    }
}

__global__ void mul_kernel(const float* __restrict__ a, const float* __restrict__ b,
                           float* __restrict__ out)
{
    int i = blockIdx.x * blockDim.x + threadIdx.x;
    if (i < Nn * HD) out[i] = a[i] * b[i];
}

__global__ void newh_kernel(const float* __restrict__ zg, const float* __restrict__ h,
                            const float* __restrict__ ht, float* __restrict__ out)
{
    int i = blockIdx.x * blockDim.x + threadIdx.x;
    if (i < Nn * HD) out[i] = zg[i] * h[i] + (1.f - zg[i]) * ht[i];
}

__global__ void init_kernel() {
    size_t i = (size_t)blockIdx.x * blockDim.x + threadIdx.x;
    if (i < 2 * SZ_HD) g_f[O_H + i] = 0.f;  // h buffer 0, both layers
    if (i < 6) d_acc[i] = 0.0;
}

// ---------------------------------------------------------------------------
// Decoder (z_s @ z_d^T) fused with BCE partial sums
// ---------------------------------------------------------------------------
__global__ void __launch_bounds__(256)
dec_bce_kernel(const float* __restrict__ zs, const float* __restrict__ zd,
               const float* __restrict__ adj, float* __restrict__ dec)
{
    __shared__ float Ss[64][33];
    __shared__ float Sd[64][33];
    int tid = threadIdx.x;
    int bi = blockIdx.y * 64, bj = blockIdx.x * 64;
    for (int i = tid; i < 64 * 32; i += 256) {
        int r = i >> 5, c = i & 31;
        Ss[r][c] = zs[(size_t)(bi + r) * 32 + c];
        Sd[r][c] = zd[(size_t)(bj + r) * 32 + c];
    }
    __syncthreads();
    int tx = tid % 16, ty = tid / 16;
    float acc[4][4];
    #pragma unroll
    for (int i = 0; i < 4; i++)
        #pragma unroll
        for (int j = 0; j < 4; j++) acc[i][j] = 0.f;
    #pragma unroll
    for (int k = 0; k < 32; k++) {
        float a[4], b[4];
        #pragma unroll
        for (int i = 0; i < 4; i++) a[i] = Ss[ty * 4 + i][k];
        #pragma unroll
        for (int j = 0; j < 4; j++) b[j] = Sd[tx * 4 + j][k];
        #pragma unroll
        for (int i = 0; i < 4; i++)
            #pragma unroll
            for (int j = 0; j < 4; j++) acc[i][j] += a[i] * b[j];
    }
    float sa = 0.f, s1 = 0.f, s2 = 0.f;
    #pragma unroll
    for (int i = 0; i < 4; i++) {
        int r = bi + ty * 4 + i;
        #pragma unroll
        for (int j = 0; j < 4; j++) {
            int c = bj + tx * 4 + j;
            float d = acc[i][j];
            dec[(size_t)r * Nn + c] = d;
            float a = adj[(size_t)r * Nn + c];
            float lg = log1pf(expf(-fabsf(d)));
            float lsp = fminf(d, 0.f) - lg;   // log_sigmoid(d)
            float lsn = fminf(-d, 0.f) - lg;  // log_sigmoid(-d)
            sa += a; s1 += a * lsp; s2 += (1.f - a) * lsn;
        }
    }
    block_add(&d_acc[0], sa);
    block_add(&d_acc[1], s1);
    block_add(&d_acc[2], s2);
}

// ---------------------------------------------------------------------------
// KLD + per-step finalize
// ---------------------------------------------------------------------------
__device__ __forceinline__ float kterm(float m1, float s1, float m2, float s2) {
    float a = s1 + 1e-10f, b = s2 + 1e-10f;
    float dm = m1 - m2;
    return 2.f * (logf(b) - logf(a)) + (a * a + dm * dm) / (b * b) - 1.f;
}

__global__ void kld_kernel(const float* __restrict__ ms, const float* __restrict__ ss,
                           const float* __restrict__ pm, const float* __restrict__ ps,
                           const float* __restrict__ md, const float* __restrict__ sd,
                           const float* __restrict__ pmd, const float* __restrict__ psd)
{
    int i = blockIdx.x * blockDim.x + threadIdx.x;
    float v = 0.f;
    if (i < Nn * ZD)
        v = kterm(ms[i], ss[i], pm[i], ps[i]) + kterm(md[i], sd[i], pmd[i], psd[i]);
    block_add(&d_acc[3], v);
}

__global__ void finalize_kernel(float* __restrict__ out) {
    double ssum = d_acc[0], S1 = d_acc[1], S2 = d_acc[2], K = d_acc[3];
    double nn2 = (double)Nn * (double)Nn;
    double posw = (nn2 - ssum) / ssum;
    double nrm  = nn2 / ((nn2 - ssum) * 2.0);
    double nll  = nrm * ((-posw) * S1 - S2) / nn2;
    double kld  = 0.5 * K / nn2;
    d_acc[4] += kld;
    d_acc[5] += nll;
    out[0] = (float)d_acc[4];
    out[1] = (float)d_acc[5];
    d_acc[0] = 0.0; d_acc[1] = 0.0; d_acc[2] = 0.0; d_acc[3] = 0.0;
}

// ---------------------------------------------------------------------------
// Host orchestration
// ---------------------------------------------------------------------------
static inline void gemm64(const float* A, const float* B, const float* bias, float* C,
                          int Ncol, int K, int lda, int ldb, int ldc, int act, int beta)
{
    dim3 g(Ncol / 64, Nn / 64);
    if (beta == 0) {
        if (act == 0)      sgemm<64, 0, 0><<<g, 256>>>(A, B, bias, C, K, lda, ldb, ldc);
        else if (act == 1) sgemm<64, 1, 0><<<g, 256>>>(A, B, bias, C, K, lda, ldb, ldc);
        else if (act == 4) sgemm<64, 4, 0><<<g, 256>>>(A, B, bias, C, K, lda, ldb, ldc);
    } else {
        if (act == 2)      sgemm<64, 2, 1><<<g, 256>>>(A, B, bias, C, K, lda, ldb, ldc);
        else if (act == 3) sgemm<64, 3, 1><<<g, 256>>>(A, B, bias, C, K, lda, ldb, ldc);
    }
}

static inline void gemm32(const float* A, const float* B, const float* bias, float* C,
                          int K, int lda, int act)
{
    dim3 g(1, Nn / 64);
    if (act == 0)      sgemm<32, 0, 0><<<g, 128>>>(A, B, bias, C, K, lda, 32, 32);
    else if (act == 4) sgemm<32, 4, 0><<<g, 128>>>(A, B, bias, C, K, lda, 32, 32);
}

extern "C" void kernel_launch(void* const* d_in, const int* /*in_sizes*/, int /*n_in*/,
                              void* d_out, int /*out_size*/)
{
    const float* x       = (const float*)d_in[0];
    const int*   ei      = (const int*)  d_in[1];
    const float* adj     = (const float*)d_in[2];
    const float* eps_s   = (const float*)d_in[3];
    const float* eps_d   = (const float*)d_in[4];
    const float* phi_x_w = (const float*)d_in[5];
    const float* phi_z_w = (const float*)d_in[6];
    const float* gxw0    = (const float*)d_in[7];   // [3,512,256]
    const float* gxw1    = (const float*)d_in[8];   // [3,256,256]
    const float* ghw     = (const float*)d_in[9];   // [2,3,256,256]
    const float* enc_w   = (const float*)d_in[10];  // [2,512,256]
    const float* enc_b   = (const float*)d_in[11];  // [2,256]
    const float* mean_w  = (const float*)d_in[12];  // [2,256,32]
    const float* mean_b  = (const float*)d_in[13];
    const float* std_w   = (const float*)d_in[14];
    const float* std_b   = (const float*)d_in[15];
    const float* pri_w   = (const float*)d_in[16];  // [2,256,256]
    const float* pri_b   = (const float*)d_in[17];
    const float* pri_mw  = (const float*)d_in[18];  // [2,256,32]
    const float* pri_mb  = (const float*)d_in[19];
    const float* pri_sw  = (const float*)d_in[20];
    const float* pri_sb  = (const float*)d_in[21];
    float* out = (float*)d_out;
    float* dec_out = out + 2;  // [T, N, N]

    float* F = nullptr;
    cudaGetSymbolAddress((void**)&F, g_f);

    float* CAT    = F + O_CAT;
    float* CATP   = F + O_CATP;
    float* ENC_S  = F + O_ENC_S;
    float* ENC_D  = F + O_ENC_D;
    float* XW_S   = F + O_XW_S;
    float* XW_D   = F + O_XW_D;
    float* MEAN_S = F + O_MEAN_S;
    float* MEAN_D = F + O_MEAN_D;
    float* STMP_S = F + O_STMP_S;
    float* STMP_D = F + O_STMP_D;
    float* STD_S  = F + O_STD_S;
    float* STD_D  = F + O_STD_D;
    float* PRI_S  = F + O_PRI_S;
    float* PRI_D  = F + O_PRI_D;
    float* PM_S   = F + O_PM_S;
    float* PS_S   = F + O_PS_S;
    float* PM_D   = F + O_PM_D;
    float* PS_D   = F + O_PS_D;
    float* Z_S    = F + O_Z_S;
    float* Z_D    = F + O_Z_D;
    float* ZCAT   = F + O_ZCAT;
    float* GIN    = F + O_GIN;
    float* GPRE   = F + O_GPRE;
    float* HPRE   = F + O_HPRE;
    float* XPRE1  = F + O_XPRE1;
    float* TZ     = F + O_TZ;
    float* TR     = F + O_TR;
    float* TH     = F + O_TH;
    float* RH     = F + O_RH;
    float* RHP    = F + O_RHP;

    init_kernel<<<(2 * SZ_HD + 255) / 256, 256>>>();

    for (int t = 0; t < Tt; t++) {
        const float* x_t   = x + (size_t)t * Nn * XD;
        const int*   src_t = ei + (size_t)t * 2 * Ee;
        const int*   dst_t = src_t + Ee;
        const float* adj_t = adj + (size_t)t * Nn * Nn;
        const float* es_t  = eps_s + (size_t)t * SZ_ZD;
        const float* ed_t  = eps_d + (size_t)t * SZ_ZD;
        float* Hc = F + O_H + (size_t)(t & 1) * 2 * SZ_HD;
        float* Hn = F + O_H + (size_t)((t + 1) & 1) * 2 * SZ_HD;
        float* hlast = Hc + SZ_HD;  // layer NL-1
        float* dec_t = dec_out + (size_t)t * Nn * Nn;

        // --- CSR for this timestep ---
        zero_csr_kernel<<<(Nn + 255) / 256, 256>>>();
        hist_kernel<<<Ee / 256, 256>>>(dst_t);
        scan_kernel<<<1, 1024>>>();
        fill_kernel<<<Ee / 256, 256>>>(src_t, dst_t);

        // --- phi_x into CAT[:,0:256]; h_last into CAT[:,256:512] ---
        gemm64(x_t, phi_x_w, nullptr, CAT, 256, XD, XD, 256, 512, 1, 0);
        copy2d_kernel<<<(Nn * HD + 255) / 256, 256>>>(hlast, HD, CAT + 256, 512, HD);

        // --- cat_pre = gin(cat) ---
        gin_kernel<<<Nn, 128>>>((const float4*)CAT, (float4*)CATP, 128, 1);

        // --- encoders ---
        gemm64(CATP, enc_w,            enc_b,       ENC_S, 256, 512, 512, 256, 256, 1, 0);
        gemm64(CATP, enc_w + 512*256,  enc_b + 256, ENC_D, 256, 512, 512, 256, 256, 1, 0);

        // --- mean (GCN) + std (gin->softplus), via linearity ---
        gemm32(ENC_S, mean_w,           nullptr, XW_S,  256, 256, 0);
        gemm32(ENC_D, mean_w + 256*32,  nullptr, XW_D,  256, 256, 0);
        gcn_kernel<<<Nn / 16, 128>>>((const float4*)XW_S, (float4*)MEAN_S,
                                     (const float4*)mean_b);
        gcn_kernel<<<Nn / 16, 128>>>((const float4*)XW_D, (float4*)MEAN_D,
                                     (const float4*)(mean_b + 32));
        gemm32(ENC_S, std_w,            nullptr, STMP_S, 256, 256, 0);
        gemm32(ENC_D, std_w + 256*32,   nullptr, STMP_D, 256, 256, 0);
        stdsp_kernel<<<Nn / 16, 128>>>((const float4*)STMP_S, (float4*)STD_S,
                                       (const float4*)std_b);
        stdsp_kernel<<<Nn / 16, 128>>>((const float4*)STMP_D, (float4*)STD_D,
                                       (const float4*)(std_b + 32));

        // --- priors ---
        gemm64(hlast, pri_w,           pri_b,       PRI_S, 256, 256, 256, 256, 256, 1, 0);
        gemm64(hlast, pri_w + 256*256, pri_b + 256, PRI_D, 256, 256, 256, 256, 256, 1, 0);
        gemm32(PRI_S, pri_mw,          pri_mb,      PM_S, 256, 256, 0);
        gemm32(PRI_S, pri_sw,          pri_sb,      PS_S, 256, 256, 4);
        gemm32(PRI_D, pri_mw + 256*32, pri_mb + 32, PM_D, 256, 256, 0);
        gemm32(PRI_D, pri_sw + 256*32, pri_sb + 32, PS_D, 256, 256, 4);

        // --- reparameterize + phi_z ---
        z_kernel<<<(Nn * ZD + 255) / 256, 256>>>(MEAN_S, STD_S, es_t,
                                                 MEAN_D, STD_D, ed_t,
                                                 Z_S, Z_D, ZCAT);
        // g_in = [phi_x | phi_z]
        copy2d_kernel<<<(Nn * HD + 255) / 256, 256>>>(CAT, 512, GIN, 512, HD);
        gemm64(ZCAT, phi_z_w, nullptr, GIN + 256, 256, 64, 64, 256, 512, 1, 0);

        // --- decoder + fused BCE sums ---
        dec_bce_kernel<<<dim3(Nn / 64, Nn / 64), 256>>>(Z_S, Z_D, adj_t, dec_t);

        // --- KLD + per-step finalize ---
        kld_kernel<<<(Nn * ZD + 255) / 256, 256>>>(MEAN_S, STD_S, PM_S, PS_S,
                                                   MEAN_D, STD_D, PM_D, PS_D);
        finalize_kernel<<<1, 1>>>(out);

        // --- graph-GRU, 2 layers ---
        for (int l = 0; l < 2; l++) {
            const float* xi  = (l == 0) ? GIN : Hn;            // layer1 input = new_h[0]
            float* xpre      = (l == 0) ? GPRE : XPRE1;
            int Kx           = (l == 0) ? 512 : 256;
            const float* xw  = (l == 0) ? gxw0 : gxw1;
            int xwStride     = Kx * 256;
            const float* hw  = ghw + (size_t)l * 3 * 256 * 256;
            float* h_l       = Hc + (size_t)l * SZ_HD;
            float* h_out     = Hn + (size_t)l * SZ_HD;

            if (l == 0)
                gin_kernel<<<Nn, 128>>>((const float4*)xi, (float4*)xpre, 128, 1);
            else
                gin_kernel<<<Nn / 2, 128>>>((const float4*)xi, (float4*)xpre, 64, 2);
            gin_kernel<<<Nn / 2, 128>>>((const float4*)h_l, (float4*)HPRE, 64, 2);

            // z gate
            gemm64(xpre, xw,              nullptr, TZ, 256, Kx, Kx, 256, 256, 0, 0);
            gemm64(HPRE, hw,              nullptr, TZ, 256, 256, 256, 256, 256, 2, 1);
            // r gate
            gemm64(xpre, xw + xwStride,   nullptr, TR, 256, Kx, Kx, 256, 256, 0, 0);
            gemm64(HPRE, hw + 256*256,    nullptr, TR, 256, 256, 256, 256, 256, 2, 1);
            // candidate
            mul_kernel<<<(Nn * HD + 255) / 256, 256>>>(TR, h_l, RH);
            gin_kernel<<<Nn / 2, 128>>>((const float4*)RH, (float4*)RHP, 64, 2);
            gemm64(xpre, xw + 2*xwStride, nullptr, TH, 256, Kx, Kx, 256, 256, 0, 0);
            gemm64(RHP,  hw + 2*256*256,  nullptr, TH, 256, 256, 256, 256, 256, 3, 1);
            // h_new
            newh_kernel<<<(Nn * HD + 255) / 256, 256>>>(TZ, h_l, TH, h_out);
        }
    }
}

// round 5
// speedup vs baseline: 1.8876x; 1.8876x over previous
#include <cuda_runtime.h>
#include <cstdint>
#include <cstddef>

// ---------------------------------------------------------------------------
// Problem constants
// ---------------------------------------------------------------------------
#define Nn 2048
#define Ee 32768
#define Tt 12
#define XD 128
#define HD 256
#define ZD 32

constexpr size_t SZ_HD  = (size_t)Nn * HD;      // 524288
constexpr size_t SZ_2HD = (size_t)Nn * 2 * HD;  // 1048576
constexpr size_t SZ_ZD  = (size_t)Nn * ZD;      // 65536

// ---------------------------------------------------------------------------
// Scratch (single __device__ array; no runtime allocation)
// NOTE: adjacency of buffers is load-bearing for batched GEMMs:
//   ENC_S|ENC_D, XW_S|XW_D, STMP_S|STMP_D, PRI_S|PRI_D,
//   PM_S|PS_S|PM_D|PS_D (stride 2*SZ_ZD), TZ|TR|TH (stride SZ_HD)
// ---------------------------------------------------------------------------
constexpr size_t O_CAT   = 0;                    // [N,512]  (phi_x | h1)
constexpr size_t O_CATP  = O_CAT   + SZ_2HD;     // gin(cat)
constexpr size_t O_ENC_S = O_CATP  + SZ_2HD;
constexpr size_t O_ENC_D = O_ENC_S + SZ_HD;
constexpr size_t O_XW_S  = O_ENC_D + SZ_HD;      // enc_s @ mean_w
constexpr size_t O_XW_D  = O_XW_S  + SZ_ZD;
constexpr size_t O_MEAN_S= O_XW_D  + SZ_ZD;
constexpr size_t O_MEAN_D= O_MEAN_S+ SZ_ZD;
constexpr size_t O_STMP_S= O_MEAN_D+ SZ_ZD;      // enc_s @ std_w
constexpr size_t O_STMP_D= O_STMP_S+ SZ_ZD;
constexpr size_t O_STD_S = O_STMP_D+ SZ_ZD;
constexpr size_t O_STD_D = O_STD_S + SZ_ZD;
constexpr size_t O_PRI_S = O_STD_D + SZ_ZD;      // [N,256]
constexpr size_t O_PRI_D = O_PRI_S + SZ_HD;
constexpr size_t O_PM_S  = O_PRI_D + SZ_HD;
constexpr size_t O_PS_S  = O_PM_S  + SZ_ZD;
constexpr size_t O_PM_D  = O_PS_S  + SZ_ZD;
constexpr size_t O_PS_D  = O_PM_D  + SZ_ZD;
constexpr size_t O_Z_S   = O_PS_D  + SZ_ZD;
constexpr size_t O_Z_D   = O_Z_S   + SZ_ZD;
constexpr size_t O_ZCAT  = O_Z_D   + SZ_ZD;      // [N,64]
constexpr size_t O_GIN   = O_ZCAT  + (size_t)Nn * 2 * ZD;  // [N,512] (phi_x|phi_z)
constexpr size_t O_GPRE  = O_GIN   + SZ_2HD;     // gin(g_in) [N,512]
constexpr size_t O_HPRE  = O_GPRE  + SZ_2HD;     // gin(h[i]) [N,256]
constexpr size_t O_XPRE1 = O_HPRE  + SZ_HD;      // gin(new_h0) [N,256]
constexpr size_t O_TZ    = O_XPRE1 + SZ_HD;
constexpr size_t O_TR    = O_TZ    + SZ_HD;
constexpr size_t O_TH    = O_TR    + SZ_HD;
constexpr size_t O_RH    = O_TH    + SZ_HD;
constexpr size_t O_RHP   = O_RH    + SZ_HD;
constexpr size_t O_H     = O_RHP   + SZ_HD;      // 2 dbl-buffers x NL layers
constexpr size_t TOTAL_F = O_H + 4 * SZ_HD;

__device__ __align__(256) float g_f[TOTAL_F];
__device__ int    d_deg[Nn];
__device__ int    d_cursor[Nn];
__device__ int    d_rowptr[Nn + 1];
__device__ int    d_csrsrc[Ee];
__device__ float  d_degf[Nn];
__device__ float  d_dinv[Nn];
__device__ double d_acc[6];  // 0:ssum 1:S1 2:S2 3:kld-step 4:kld-total 5:nll-total

// ---------------------------------------------------------------------------
// Activations / reductions
// ---------------------------------------------------------------------------
template<int ACT>
__device__ __forceinline__ float activate(float v) {
    if (ACT == 1) return fmaxf(v, 0.f);
    if (ACT == 2) return 1.f / (1.f + expf(-v));
    if (ACT == 3) return tanhf(v);
    if (ACT == 4) return fmaxf(v, 0.f) + log1pf(expf(-fabsf(v)));  // softplus
    return v;
}

__device__ __forceinline__ void block_add(double* target, float v) {
    #pragma unroll
    for (int o = 16; o; o >>= 1) v += __shfl_down_sync(0xffffffffu, v, o);
    __shared__ float wsum[32];
    int lane = threadIdx.x & 31, wid = threadIdx.x >> 5;
    if (lane == 0) wsum[wid] = v;
    __syncthreads();
    if (threadIdx.x == 0) {
        float s = 0.f;
        int nw = (blockDim.x + 31) >> 5;
        for (int i = 0; i < nw; i++) s += wsum[i];
        atomicAdd(target, (double)s);
    }
    __syncthreads();
}

// ---------------------------------------------------------------------------
// SGEMM 64x64x16, 128 threads, 8x4 micro-tile, float4 everywhere.
// Batched over gridDim.z via element strides.
// C = act( A[M,K]@B[K,N] (+C if BETA) (+bias) )
// ---------------------------------------------------------------------------
template<int ACT, int BETA>
__global__ void __launch_bounds__(128)
sgemm64(const float* __restrict__ A, const float* __restrict__ B,
        const float* __restrict__ bias, float* __restrict__ C,
        int K, int lda, int ldb, int ldc,
        size_t sA, size_t sB, size_t sBias, size_t sC)
{
    constexpr int BK = 16;
    __shared__ float4 As[BK][16];   // As[k][m/4]: 64 floats per k-row
    __shared__ float4 Bs[BK][16];   // Bs[k][n/4]

    const int z = blockIdx.z;
    A += (size_t)z * sA;
    B += (size_t)z * sB;
    C += (size_t)z * sC;
    const float* biasz = bias ? bias + (size_t)z * sBias : nullptr;

    const int tid = threadIdx.x;
    const int bm = blockIdx.y * 64, bn = blockIdx.x * 64;
    const int tx = tid & 15;        // n-block: tx*4
    const int ty = tid >> 4;        // m-block: ty*8

    float acc[8][4];
    #pragma unroll
    for (int i = 0; i < 8; i++)
        #pragma unroll
        for (int j = 0; j < 4; j++) acc[i][j] = 0.f;

    float* Asf = (float*)As;

    for (int k0 = 0; k0 < K; k0 += BK) {
        // Stage A (transposed): 64 rows x 16 k = 256 float4 loads
        #pragma unroll
        for (int it = 0; it < 2; it++) {
            int idx = tid + it * 128;
            int m = idx >> 2, c4 = idx & 3;         // c4: which 4-k group
            float4 v = *(const float4*)&A[(size_t)(bm + m) * lda + k0 + c4 * 4];
            Asf[(c4 * 4 + 0) * 64 + m] = v.x;
            Asf[(c4 * 4 + 1) * 64 + m] = v.y;
            Asf[(c4 * 4 + 2) * 64 + m] = v.z;
            Asf[(c4 * 4 + 3) * 64 + m] = v.w;
        }
        // Stage B: 16 k x 64 n = 256 float4 loads
        #pragma unroll
        for (int it = 0; it < 2; it++) {
            int idx = tid + it * 128;
            int k = idx >> 4, n4 = idx & 15;
            Bs[k][n4] = *(const float4*)&B[(size_t)(k0 + k) * ldb + bn + n4 * 4];
        }
        __syncthreads();
        #pragma unroll
        for (int k = 0; k < BK; k++) {
            float4 a0 = As[k][ty * 2];
            float4 a1 = As[k][ty * 2 + 1];
            float4 b  = Bs[k][tx];
            float av[8] = {a0.x, a0.y, a0.z, a0.w, a1.x, a1.y, a1.z, a1.w};
            float bv[4] = {b.x, b.y, b.z, b.w};
            #pragma unroll
            for (int i = 0; i < 8; i++)
                #pragma unroll
                for (int j = 0; j < 4; j++) acc[i][j] += av[i] * bv[j];
        }
        __syncthreads();
    }

    const int n = bn + tx * 4;
    float4 bb = make_float4(0.f, 0.f, 0.f, 0.f);
    if (biasz) bb = *(const float4*)&biasz[n];
    #pragma unroll
    for (int i = 0; i < 8; i++) {
        int m = bm + ty * 8 + i;
        float4 r = make_float4(acc[i][0], acc[i][1], acc[i][2], acc[i][3]);
        if (BETA) {
            float4 c = *(const float4*)&C[(size_t)m * ldc + n];
            r.x += c.x; r.y += c.y; r.z += c.z; r.w += c.w;
        }
        r.x = activate<ACT>(r.x + bb.x);
        r.y = activate<ACT>(r.y + bb.y);
        r.z = activate<ACT>(r.z + bb.z);
        r.w = activate<ACT>(r.w + bb.w);
        *(float4*)&C[(size_t)m * ldc + n] = r;
    }
}

// 64x32x16 variant for the ZD=32 GEMMs. 128 threads, 4x4 micro-tile.
template<int ACT>
__global__ void __launch_bounds__(128)
sgemm32(const float* __restrict__ A, const float* __restrict__ B,
        const float* __restrict__ bias, float* __restrict__ C,
        int K, int lda,
        size_t sA, size_t sB, size_t sBias, size_t sC)
{
    constexpr int BK = 16;
    __shared__ float4 As[BK][16];
    __shared__ float4 Bs[BK][8];

    const int z = blockIdx.z;
    A += (size_t)z * sA;
    B += (size_t)z * sB;
    C += (size_t)z * sC;
    const float* biasz = bias ? bias + (size_t)z * sBias : nullptr;

    const int tid = threadIdx.x;
    const int bm = blockIdx.y * 64;
    const int tx = tid & 7;     // n: tx*4
    const int ty = tid >> 3;    // m: ty*4  (0..15)

    float acc[4][4];
    #pragma unroll
    for (int i = 0; i < 4; i++)
        #pragma unroll
        for (int j = 0; j < 4; j++) acc[i][j] = 0.f;

    float* Asf = (float*)As;

    for (int k0 = 0; k0 < K; k0 += BK) {
        #pragma unroll
        for (int it = 0; it < 2; it++) {
            int idx = tid + it * 128;
            int m = idx >> 2, c4 = idx & 3;
            float4 v = *(const float4*)&A[(size_t)(bm + m) * lda + k0 + c4 * 4];
            Asf[(c4 * 4 + 0) * 64 + m] = v.x;
            Asf[(c4 * 4 + 1) * 64 + m] = v.y;
            Asf[(c4 * 4 + 2) * 64 + m] = v.z;
            Asf[(c4 * 4 + 3) * 64 + m] = v.w;
        }
        {
            int k = tid >> 3, n4 = tid & 7;   // 128 threads = 16x8 exactly
            Bs[k][n4] = *(const float4*)&B[(size_t)(k0 + k) * 32 + n4 * 4];
        }
        __syncthreads();
        #pragma unroll
        for (int k = 0; k < BK; k++) {
            float4 a = As[k][ty];
            float4 b = Bs[k][tx];
            float av[4] = {a.x, a.y, a.z, a.w};
            float bv[4] = {b.x, b.y, b.z, b.w};
            #pragma unroll
            for (int i = 0; i < 4; i++)
                #pragma unroll
                for (int j = 0; j < 4; j++) acc[i][j] += av[i] * bv[j];
        }
        __syncthreads();
    }

    const int n = tx * 4;
    float4 bb = make_float4(0.f, 0.f, 0.f, 0.f);
    if (biasz) bb = *(const float4*)&biasz[n];
    #pragma unroll
    for (int i = 0; i < 4; i++) {
        int m = bm + ty * 4 + i;
        float4 r = make_float4(acc[i][0] + bb.x, acc[i][1] + bb.y,
                               acc[i][2] + bb.z, acc[i][3] + bb.w);
        r.x = activate<ACT>(r.x); r.y = activate<ACT>(r.y);
        r.z = activate<ACT>(r.z); r.w = activate<ACT>(r.w);
        *(float4*)&C[(size_t)m * 32 + n] = r;
    }
}

// ---------------------------------------------------------------------------
// CSR build
// ---------------------------------------------------------------------------
__global__ void zero_csr_kernel() {
    int i = blockIdx.x * blockDim.x + threadIdx.x;
    if (i < Nn) { d_deg[i] = 0; d_cursor[i] = 0; }
}
__global__ void hist_kernel(const int* __restrict__ dst) {
    int i = blockIdx.x * blockDim.x + threadIdx.x;
    if (i < Ee) atomicAdd(&d_deg[dst[i]], 1);
}
__global__ void scan_kernel() {
    __shared__ int s0[2048], s1[2048];
    int t = threadIdx.x;  // 1024 threads
    s0[t] = d_deg[t]; s0[t + 1024] = d_deg[t + 1024];
    __syncthreads();
    int* cur = s0; int* nxt = s1;
    for (int off = 1; off < 2048; off <<= 1) {
        int i0 = t, i1 = t + 1024;
        nxt[i0] = cur[i0] + (i0 >= off ? cur[i0 - off] : 0);
        nxt[i1] = cur[i1] + (i1 >= off ? cur[i1 - off] : 0);
        __syncthreads();
        int* tmp = cur; cur = nxt; nxt = tmp;
    }
    d_rowptr[t + 1]    = cur[t];
    d_rowptr[t + 1025] = cur[t + 1024];
    if (t == 0) d_rowptr[0] = 0;
    float f0 = (float)(d_deg[t] + 1);
    float f1 = (float)(d_deg[t + 1024] + 1);
    d_degf[t] = f0;          d_dinv[t] = rsqrtf(f0);
    d_degf[t + 1024] = f1;   d_dinv[t + 1024] = rsqrtf(f1);
}
__global__ void fill_kernel(const int* __restrict__ src, const int* __restrict__ dst) {
    int i = blockIdx.x * blockDim.x + threadIdx.x;
    if (i < Ee) {
        int d = dst[i];
        int pos = atomicAdd(&d_cursor[d], 1);
        d_csrsrc[d_rowptr[d] + pos] = src[i];
    }
}

// ---------------------------------------------------------------------------
// Graph gathers
// ---------------------------------------------------------------------------
__global__ void gin_kernel(const float4* __restrict__ x, float4* __restrict__ out,
                           int D4, int npb)
{
    int lane = threadIdx.x % D4;
    int n = blockIdx.x * npb + threadIdx.x / D4;
    int beg = d_rowptr[n], end = d_rowptr[n + 1];
    float4 acc = x[(size_t)n * D4 + lane];
    for (int e = beg; e < end; e++) {
        float4 v = x[(size_t)d_csrsrc[e] * D4 + lane];
        acc.x += v.x; acc.y += v.y; acc.z += v.z; acc.w += v.w;
    }
    out[(size_t)n * D4 + lane] = acc;
}

__global__ void gcn_kernel(const float4* __restrict__ xw, float4* __restrict__ out,
                           const float4* __restrict__ bias)
{
    int lane = threadIdx.x & 7;
    int n = blockIdx.x * 16 + (threadIdx.x >> 3);
    int beg = d_rowptr[n], end = d_rowptr[n + 1];
    float4 acc = make_float4(0.f, 0.f, 0.f, 0.f);
    for (int e = beg; e < end; e++) {
        int s = d_csrsrc[e];
        float w = d_dinv[s];
        float4 v = xw[(size_t)s * 8 + lane];
        acc.x += w * v.x; acc.y += w * v.y; acc.z += w * v.z; acc.w += w * v.w;
    }
    float dn = d_dinv[n], id = 1.f / d_degf[n];
    float4 xn = xw[(size_t)n * 8 + lane];
    float4 b = bias[lane];
    out[(size_t)n * 8 + lane] = make_float4(
        dn * acc.x + id * xn.x + b.x, dn * acc.y + id * xn.y + b.y,
        dn * acc.z + id * xn.z + b.z, dn * acc.w + id * xn.w + b.w);
}

__global__ void stdsp_kernel(const float4* __restrict__ tmp, float4* __restrict__ out,
                             const float4* __restrict__ bias)
{
    int lane = threadIdx.x & 7;
    int n = blockIdx.x * 16 + (threadIdx.x >> 3);
    int beg = d_rowptr[n], end = d_rowptr[n + 1];
    float4 acc = tmp[(size_t)n * 8 + lane];
    for (int e = beg; e < end; e++) {
        float4 v = tmp[(size_t)d_csrsrc[e] * 8 + lane];
        acc.x += v.x; acc.y += v.y; acc.z += v.z; acc.w += v.w;
    }
    float4 b = bias[lane];
    out[(size_t)n * 8 + lane] = make_float4(
        activate<4>(acc.x + b.x), activate<4>(acc.y + b.y),
        activate<4>(acc.z + b.z), activate<4>(acc.w + b.w));
}

// ---------------------------------------------------------------------------
// Elementwise
// ---------------------------------------------------------------------------
__global__ void copy2d_kernel(const float* __restrict__ src, int lds,
                              float* __restrict__ dst, int ldd, int D)
{
    int i = blockIdx.x * blockDim.x + threadIdx.x;
    if (i < Nn * D) {
        int n = i / D, j = i % D;
        dst[(size_t)n * ldd + j] = src[(size_t)n * lds + j];
    }
}

__global__ void z_kernel(const float* __restrict__ ms, const float* __restrict__ ss,
                         const float* __restrict__ es, const float* __restrict__ md,
                         const float* __restrict__ sd, const float* __restrict__ ed,
                         float* __restrict__ zs, float* __restrict__ zd,
                         float* __restrict__ zcat)
{
    int i = blockIdx.x * blockDim.x + threadIdx.x;
    if (i < Nn * ZD) {
        int n = i >> 5, j = i & 31;
        float a = ms[i] + ss[i] * es[i];
        float b = md[i] + sd[i] * ed[i];
        zs[i] = a; zd[i] = b;
        zcat[(size_t)n * 64 + j] = a;
        zcat[(size_t)n * 64 + 32 + j] = b;
    }
}

__global__ void mul_kernel(const float* __restrict__ a, const float* __restrict__ b,
                           float* __restrict__ out)
{
    int i = blockIdx.x * blockDim.x + threadIdx.x;
    if (i < Nn * HD) out[i] = a[i] * b[i];
}

__global__ void newh_kernel(const float* __restrict__ zg, const float* __restrict__ h,
                            const float* __restrict__ ht, float* __restrict__ out)
{
    int i = blockIdx.x * blockDim.x + threadIdx.x;
    if (i < Nn * HD) out[i] = zg[i] * h[i] + (1.f - zg[i]) * ht[i];
}

__global__ void init_kernel() {
    size_t i = (size_t)blockIdx.x * blockDim.x + threadIdx.x;
    if (i < 2 * SZ_HD) g_f[O_H + i] = 0.f;
    if (i < 6) d_acc[i] = 0.0;
}

// ---------------------------------------------------------------------------
// Decoder (z_s @ z_d^T) fused with BCE partial sums
// ---------------------------------------------------------------------------
__global__ void __launch_bounds__(256)
dec_bce_kernel(const float* __restrict__ zs, const float* __restrict__ zd,
               const float* __restrict__ adj, float* __restrict__ dec)
{
    __shared__ float Ss[64][33];
    __shared__ float Sd[64][33];
    int tid = threadIdx.x;
    int bi = blockIdx.y * 64, bj = blockIdx.x * 64;
    for (int i = tid; i < 64 * 32; i += 256) {
        int r = i >> 5, c = i & 31;
        Ss[r][c] = zs[(size_t)(bi + r) * 32 + c];
        Sd[r][c] = zd[(size_t)(bj + r) * 32 + c];
    }
    __syncthreads();
    int tx = tid % 16, ty = tid / 16;
    float acc[4][4];
    #pragma unroll
    for (int i = 0; i < 4; i++)
        #pragma unroll
        for (int j = 0; j < 4; j++) acc[i][j] = 0.f;
    #pragma unroll
    for (int k = 0; k < 32; k++) {
        float a[4], b[4];
        #pragma unroll
        for (int i = 0; i < 4; i++) a[i] = Ss[ty * 4 + i][k];
        #pragma unroll
        for (int j = 0; j < 4; j++) b[j] = Sd[tx * 4 + j][k];
        #pragma unroll
        for (int i = 0; i < 4; i++)
            #pragma unroll
            for (int j = 0; j < 4; j++) acc[i][j] += a[i] * b[j];
    }
    float sa = 0.f, s1 = 0.f, s2 = 0.f;
    #pragma unroll
    for (int i = 0; i < 4; i++) {
        int r = bi + ty * 4 + i;
        #pragma unroll
        for (int j = 0; j < 4; j++) {
            int c = bj + tx * 4 + j;
            float d = acc[i][j];
            dec[(size_t)r * Nn + c] = d;
            float a = adj[(size_t)r * Nn + c];
            float lg = log1pf(expf(-fabsf(d)));
            float lsp = fminf(d, 0.f) - lg;
            float lsn = fminf(-d, 0.f) - lg;
            sa += a; s1 += a * lsp; s2 += (1.f - a) * lsn;
        }
    }
    block_add(&d_acc[0], sa);
    block_add(&d_acc[1], s1);
    block_add(&d_acc[2], s2);
}

// ---------------------------------------------------------------------------
// KLD + per-step finalize
// ---------------------------------------------------------------------------
__device__ __forceinline__ float kterm(float m1, float s1, float m2, float s2) {
    float a = s1 + 1e-10f, b = s2 + 1e-10f;
    float dm = m1 - m2;
    return 2.f * (logf(b) - logf(a)) + (a * a + dm * dm) / (b * b) - 1.f;
}

__global__ void kld_kernel(const float* __restrict__ ms, const float* __restrict__ ss,
                           const float* __restrict__ pm, const float* __restrict__ ps,
                           const float* __restrict__ md, const float* __restrict__ sd,
                           const float* __restrict__ pmd, const float* __restrict__ psd)
{
    int i = blockIdx.x * blockDim.x + threadIdx.x;
    float v = 0.f;
    if (i < Nn * ZD)
        v = kterm(ms[i], ss[i], pm[i], ps[i]) + kterm(md[i], sd[i], pmd[i], psd[i]);
    block_add(&d_acc[3], v);
}

__global__ void finalize_kernel(float* __restrict__ out) {
    double ssum = d_acc[0], S1 = d_acc[1], S2 = d_acc[2], K = d_acc[3];
    double nn2 = (double)Nn * (double)Nn;
    double posw = (nn2 - ssum) / ssum;
    double nrm  = nn2 / ((nn2 - ssum) * 2.0);
    double nll  = nrm * ((-posw) * S1 - S2) / nn2;
    double kld  = 0.5 * K / nn2;
    d_acc[4] += kld;
    d_acc[5] += nll;
    out[0] = (float)d_acc[4];
    out[1] = (float)d_acc[5];
    d_acc[0] = 0.0; d_acc[1] = 0.0; d_acc[2] = 0.0; d_acc[3] = 0.0;
}

// ---------------------------------------------------------------------------
// Host launch helpers
// ---------------------------------------------------------------------------
static inline void g64(const float* A, const float* B, const float* bias, float* C,
                       int Ncol, int K, int lda, int ldb, int ldc, int act, int beta,
                       int z, size_t sA, size_t sB, size_t sBias, size_t sC)
{
    dim3 g(Ncol / 64, Nn / 64, z);
    if (beta == 0) {
        if (act == 0)      sgemm64<0, 0><<<g, 128>>>(A, B, bias, C, K, lda, ldb, ldc, sA, sB, sBias, sC);
        else if (act == 1) sgemm64<1, 0><<<g, 128>>>(A, B, bias, C, K, lda, ldb, ldc, sA, sB, sBias, sC);
    } else {
        if (act == 2)      sgemm64<2, 1><<<g, 128>>>(A, B, bias, C, K, lda, ldb, ldc, sA, sB, sBias, sC);
        else if (act == 3) sgemm64<3, 1><<<g, 128>>>(A, B, bias, C, K, lda, ldb, ldc, sA, sB, sBias, sC);
    }
}

static inline void g32(const float* A, const float* B, const float* bias, float* C,
                       int K, int lda, int act,
                       int z, size_t sA, size_t sB, size_t sBias, size_t sC)
{
    dim3 g(1, Nn / 64, z);
    if (act == 0)      sgemm32<0><<<g, 128>>>(A, B, bias, C, K, lda, sA, sB, sBias, sC);
    else if (act == 4) sgemm32<4><<<g, 128>>>(A, B, bias, C, K, lda, sA, sB, sBias, sC);
}

extern "C" void kernel_launch(void* const* d_in, const int* /*in_sizes*/, int /*n_in*/,
                              void* d_out, int /*out_size*/)
{
    const float* x       = (const float*)d_in[0];
    const int*   ei      = (const int*)  d_in[1];
    const float* adj     = (const float*)d_in[2];
    const float* eps_s   = (const float*)d_in[3];
    const float* eps_d   = (const float*)d_in[4];
    const float* phi_x_w = (const float*)d_in[5];
    const float* phi_z_w = (const float*)d_in[6];
    const float* gxw0    = (const float*)d_in[7];   // [3,512,256]
    const float* gxw1    = (const float*)d_in[8];   // [3,256,256]
    const float* ghw     = (const float*)d_in[9];   // [2,3,256,256]
    const float* enc_w   = (const float*)d_in[10];  // [2,512,256]
    const float* enc_b   = (const float*)d_in[11];  // [2,256]
    const float* mean_w  = (const float*)d_in[12];  // [2,256,32]
    const float* mean_b  = (const float*)d_in[13];
    const float* std_w   = (const float*)d_in[14];
    const float* std_b   = (const float*)d_in[15];
    const float* pri_w   = (const float*)d_in[16];  // [2,256,256]
    const float* pri_b   = (const float*)d_in[17];
    const float* pri_mw  = (const float*)d_in[18];  // [2,256,32]
    const float* pri_mb  = (const float*)d_in[19];
    const float* pri_sw  = (const float*)d_in[20];
    const float* pri_sb  = (const float*)d_in[21];
    float* out = (float*)d_out;
    float* dec_out = out + 2;  // [T, N, N]

    float* F = nullptr;
    cudaGetSymbolAddress((void**)&F, g_f);

    float* CAT    = F + O_CAT;
    float* CATP   = F + O_CATP;
    float* ENC_S  = F + O_ENC_S;
    float* XW_S   = F + O_XW_S;
    float* XW_D   = F + O_XW_D;
    float* MEAN_S = F + O_MEAN_S;
    float* MEAN_D = F + O_MEAN_D;
    float* STMP_S = F + O_STMP_S;
    float* STMP_D = F + O_STMP_D;
    float* STD_S  = F + O_STD_S;
    float* STD_D  = F + O_STD_D;
    float* PRI_S  = F + O_PRI_S;
    float* PM_S   = F + O_PM_S;
    float* PS_S   = F + O_PS_S;
    float* PM_D   = F + O_PM_D;
    float* PS_D   = F + O_PS_D;
    float* Z_S    = F + O_Z_S;
    float* Z_D    = F + O_Z_D;
    float* ZCAT   = F + O_ZCAT;
    float* GIN    = F + O_GIN;
    float* GPRE   = F + O_GPRE;
    float* HPRE   = F + O_HPRE;
    float* XPRE1  = F + O_XPRE1;
    float* TZ     = F + O_TZ;
    float* TH     = F + O_TH;
    float* RH     = F + O_RH;
    float* RHP    = F + O_RHP;

    init_kernel<<<(2 * SZ_HD + 255) / 256, 256>>>();

    for (int t = 0; t < Tt; t++) {
        const float* x_t   = x + (size_t)t * Nn * XD;
        const int*   src_t = ei + (size_t)t * 2 * Ee;
        const int*   dst_t = src_t + Ee;
        const float* adj_t = adj + (size_t)t * Nn * Nn;
        const float* es_t  = eps_s + (size_t)t * SZ_ZD;
        const float* ed_t  = eps_d + (size_t)t * SZ_ZD;
        float* Hc = F + O_H + (size_t)(t & 1) * 2 * SZ_HD;
        float* Hn = F + O_H + (size_t)((t + 1) & 1) * 2 * SZ_HD;
        float* hlast = Hc + SZ_HD;
        float* dec_t = dec_out + (size_t)t * Nn * Nn;

        // --- CSR for this timestep ---
        zero_csr_kernel<<<(Nn + 255) / 256, 256>>>();
        hist_kernel<<<Ee / 256, 256>>>(dst_t);
        scan_kernel<<<1, 1024>>>();
        fill_kernel<<<Ee / 256, 256>>>(src_t, dst_t);

        // --- phi_x into CAT[:,0:256]; h_last into CAT[:,256:512] ---
        g64(x_t, phi_x_w, nullptr, CAT, 256, XD, XD, 256, 512, 1, 0, 1, 0, 0, 0, 0);
        copy2d_kernel<<<(Nn * HD + 255) / 256, 256>>>(hlast, HD, CAT + 256, 512, HD);

        // --- cat_pre = gin(cat) ---
        gin_kernel<<<Nn, 128>>>((const float4*)CAT, (float4*)CATP, 128, 1);

        // --- encoders (batched z=2) ---
        g64(CATP, enc_w, enc_b, ENC_S, 256, 512, 512, 256, 256, 1, 0,
            2, 0, 512 * 256, 256, SZ_HD);

        // --- mean/std temporaries (batched z=2 each) ---
        g32(ENC_S, mean_w, nullptr, XW_S, 256, 256, 0, 2, SZ_HD, 256 * 32, 0, SZ_ZD);
        g32(ENC_S, std_w,  nullptr, STMP_S, 256, 256, 0, 2, SZ_HD, 256 * 32, 0, SZ_ZD);
        gcn_kernel<<<Nn / 16, 128>>>((const float4*)XW_S, (float4*)MEAN_S,
                                     (const float4*)mean_b);
        gcn_kernel<<<Nn / 16, 128>>>((const float4*)XW_D, (float4*)MEAN_D,
                                     (const float4*)(mean_b + 32));
        stdsp_kernel<<<Nn / 16, 128>>>((const float4*)STMP_S, (float4*)STD_S,
                                       (const float4*)std_b);
        stdsp_kernel<<<Nn / 16, 128>>>((const float4*)STMP_D, (float4*)STD_D,
                                       (const float4*)(std_b + 32));

        // --- priors (batched) ---
        g64(hlast, pri_w, pri_b, PRI_S, 256, 256, 256, 256, 256, 1, 0,
            2, 0, 256 * 256, 256, SZ_HD);
        g32(PRI_S, pri_mw, pri_mb, PM_S, 256, 256, 0, 2, SZ_HD, 256 * 32, 32, 2 * SZ_ZD);
        g32(PRI_S, pri_sw, pri_sb, PS_S, 256, 256, 4, 2, SZ_HD, 256 * 32, 32, 2 * SZ_ZD);

        // --- reparameterize + phi_z ---
        z_kernel<<<(Nn * ZD + 255) / 256, 256>>>(MEAN_S, STD_S, es_t,
                                                 MEAN_D, STD_D, ed_t,
                                                 Z_S, Z_D, ZCAT);
        copy2d_kernel<<<(Nn * HD + 255) / 256, 256>>>(CAT, 512, GIN, 512, HD);
        g64(ZCAT, phi_z_w, nullptr, GIN + 256, 256, 64, 64, 256, 512, 1, 0, 1, 0, 0, 0, 0);

        // --- decoder + fused BCE sums ---
        dec_bce_kernel<<<dim3(Nn / 64, Nn / 64), 256>>>(Z_S, Z_D, adj_t, dec_t);

        // --- KLD + per-step finalize ---
        kld_kernel<<<(Nn * ZD + 255) / 256, 256>>>(MEAN_S, STD_S, PM_S, PS_S,
                                                   MEAN_D, STD_D, PM_D, PS_D);
        finalize_kernel<<<1, 1>>>(out);

        // --- graph-GRU, 2 layers ---
        for (int l = 0; l < 2; l++) {
            const float* xi  = (l == 0) ? GIN : Hn;
            float* xpre      = (l == 0) ? GPRE : XPRE1;
            int Kx           = (l == 0) ? 512 : 256;
            const float* xw  = (l == 0) ? gxw0 : gxw1;
            const float* hw  = ghw + (size_t)l * 3 * 256 * 256;
            float* h_l       = Hc + (size_t)l * SZ_HD;
            float* h_out     = Hn + (size_t)l * SZ_HD;

            if (l == 0)
                gin_kernel<<<Nn, 128>>>((const float4*)xi, (float4*)xpre, 128, 1);
            else
                gin_kernel<<<Nn / 2, 128>>>((const float4*)xi, (float4*)xpre, 64, 2);
            gin_kernel<<<Nn / 2, 128>>>((const float4*)h_l, (float4*)HPRE, 64, 2);

            // x-side of all 3 gates in one batched launch -> TZ|TR|TH
            g64(xpre, xw, nullptr, TZ, 256, Kx, Kx, 256, 256, 0, 0,
                3, 0, (size_t)Kx * 256, 0, SZ_HD);
            // h-side of z,r gates: sigmoid(+beta), batched z=2 -> TZ|TR
            g64(HPRE, hw, nullptr, TZ, 256, 256, 256, 256, 256, 2, 1,
                2, 0, 256 * 256, 0, SZ_HD);
            // candidate
            mul_kernel<<<(Nn * HD + 255) / 256, 256>>>(TZ + SZ_HD, h_l, RH);  // TR
            gin_kernel<<<Nn / 2, 128>>>((const float4*)RH, (float4*)RHP, 64, 2);
            g64(RHP, hw + 2 * 256 * 256, nullptr, TH, 256, 256, 256, 256, 256, 3, 1,
                1, 0, 0, 0, 0);
            // h_new
            newh_kernel<<<(Nn * HD + 255) / 256, 256>>>(TZ, h_l, TH, h_out);
        }
    }
}

// round 7
// speedup vs baseline: 2.0090x; 1.0643x over previous
#include <cuda_runtime.h>
#include <cstdint>
#include <cstddef>

// ---------------------------------------------------------------------------
// Problem constants
// ---------------------------------------------------------------------------
#define Nn 2048
#define Ee 32768
#define Tt 12
#define XD 128
#define HD 256
#define ZD 32

constexpr size_t SZ_HD  = (size_t)Nn * HD;      // 524288
constexpr size_t SZ_2HD = (size_t)Nn * 2 * HD;  // 1048576
constexpr size_t SZ_ZD  = (size_t)Nn * ZD;      // 65536

// ---------------------------------------------------------------------------
// Scratch layout (adjacency is load-bearing for batched GEMMs)
// ---------------------------------------------------------------------------
constexpr size_t O_CAT   = 0;                    // [N,512]  (phi_x | h1) == GIN
constexpr size_t O_CATP  = O_CAT   + SZ_2HD;     // gin(cat)
constexpr size_t O_ENC_S = O_CATP  + SZ_2HD;
constexpr size_t O_ENC_D = O_ENC_S + SZ_HD;
constexpr size_t O_XW_S  = O_ENC_D + SZ_HD;
constexpr size_t O_XW_D  = O_XW_S  + SZ_ZD;
constexpr size_t O_MEAN_S= O_XW_D  + SZ_ZD;
constexpr size_t O_MEAN_D= O_MEAN_S+ SZ_ZD;
constexpr size_t O_STMP_S= O_MEAN_D+ SZ_ZD;
constexpr size_t O_STMP_D= O_STMP_S+ SZ_ZD;
constexpr size_t O_STD_S = O_STMP_D+ SZ_ZD;
constexpr size_t O_STD_D = O_STD_S + SZ_ZD;
constexpr size_t O_PRI_S = O_STD_D + SZ_ZD;
constexpr size_t O_PRI_D = O_PRI_S + SZ_HD;
constexpr size_t O_PM_S  = O_PRI_D + SZ_HD;
constexpr size_t O_PS_S  = O_PM_S  + SZ_ZD;
constexpr size_t O_PM_D  = O_PS_S  + SZ_ZD;
constexpr size_t O_PS_D  = O_PM_D  + SZ_ZD;
constexpr size_t O_Z_S   = O_PS_D  + SZ_ZD;
constexpr size_t O_Z_D   = O_Z_S   + SZ_ZD;
constexpr size_t O_ZCAT  = O_Z_D   + SZ_ZD;      // [N,64]
constexpr size_t O_GPRE  = O_ZCAT  + (size_t)Nn * 2 * ZD;  // gin(g_in) [N,512]
constexpr size_t O_HPRE  = O_GPRE  + SZ_2HD;     // gin(h[i]) [N,256]
constexpr size_t O_XPRE1 = O_HPRE  + SZ_HD;      // gin(new_h0) [N,256]
constexpr size_t O_TZ    = O_XPRE1 + SZ_HD;
constexpr size_t O_TR    = O_TZ    + SZ_HD;
constexpr size_t O_TH    = O_TR    + SZ_HD;
constexpr size_t O_RH    = O_TH    + SZ_HD;
constexpr size_t O_RHP   = O_RH    + SZ_HD;
constexpr size_t O_H     = O_RHP   + SZ_HD;      // 2 dbl-buffers x NL layers
constexpr size_t TOTAL_F = O_H + 4 * SZ_HD;

__device__ __align__(256) float g_f[TOTAL_F];
__device__ int    d_deg[Nn];
__device__ int    d_cursor[Nn];
__device__ int    d_rowptr[Nn + 1];
__device__ int    d_csrsrc[Ee];
__device__ float  d_degf[Nn];
__device__ float  d_dinv[Nn];
__device__ double d_acc[6];

// ---------------------------------------------------------------------------
// f32x2 packed-FMA helpers (Blackwell FFMA2 via PTX)
// ---------------------------------------------------------------------------
typedef unsigned long long u64;

__device__ __forceinline__ u64 pack2(float x, float y) {
    u64 r; asm("mov.b64 %0, {%1, %2};" : "=l"(r) : "f"(x), "f"(y)); return r;
}
__device__ __forceinline__ void ffma2(u64& c, u64 a, u64 b) {
    asm("fma.rn.f32x2 %0, %1, %2, %0;" : "+l"(c) : "l"(a), "l"(b));
}
__device__ __forceinline__ float2 unpack2(u64 v) {
    float2 r; asm("mov.b64 {%0, %1}, %2;" : "=f"(r.x), "=f"(r.y) : "l"(v)); return r;
}

// ---------------------------------------------------------------------------
// Activations / reductions
// ---------------------------------------------------------------------------
template<int ACT>
__device__ __forceinline__ float activate(float v) {
    if (ACT == 1) return fmaxf(v, 0.f);
    if (ACT == 2) return 1.f / (1.f + expf(-v));
    if (ACT == 3) return tanhf(v);
    if (ACT == 4) return fmaxf(v, 0.f) + log1pf(expf(-fabsf(v)));  // softplus
    return v;
}

__device__ __forceinline__ void block_add(double* target, float v) {
    #pragma unroll
    for (int o = 16; o; o >>= 1) v += __shfl_down_sync(0xffffffffu, v, o);
    __shared__ float wsum[32];
    int lane = threadIdx.x & 31, wid = threadIdx.x >> 5;
    if (lane == 0) wsum[wid] = v;
    __syncthreads();
    if (threadIdx.x == 0) {
        float s = 0.f;
        int nw = (blockDim.x + 31) >> 5;
        for (int i = 0; i < nw; i++) s += wsum[i];
        atomicAdd(target, (double)s);
    }
    __syncthreads();
}

// ---------------------------------------------------------------------------
// 64x64x16 mainloop (128 threads, 8x4 micro-tile, FFMA2).
// acc[i2][j] packs output rows (2*i2, 2*i2+1) for column j.
// A-smem stride is exactly 64 floats -> all u64 reads 8B-aligned.
// ---------------------------------------------------------------------------
__device__ __forceinline__ void mainloop64(
    const float* __restrict__ A, const float* __restrict__ B,
    int K, int lda, int ldb, int bm, int bn,
    float4 (*As)[16], float4 (*Bs)[16], u64 acc[4][4])
{
    const int tid = threadIdx.x;
    const int tx = tid & 15;   // n-block: tx*4
    const int ty = tid >> 4;   // m-block: ty*8
    float* Asf = (float*)As;

    for (int k0 = 0; k0 < K; k0 += 16) {
        #pragma unroll
        for (int it = 0; it < 2; it++) {
            int idx = tid + it * 128;
            int m = idx >> 2, c4 = idx & 3;
            float4 v = *(const float4*)&A[(size_t)(bm + m) * lda + k0 + c4 * 4];
            Asf[(c4 * 4 + 0) * 64 + m] = v.x;
            Asf[(c4 * 4 + 1) * 64 + m] = v.y;
            Asf[(c4 * 4 + 2) * 64 + m] = v.z;
            Asf[(c4 * 4 + 3) * 64 + m] = v.w;
        }
        #pragma unroll
        for (int it = 0; it < 2; it++) {
            int idx = tid + it * 128;
            int k = idx >> 4, n4 = idx & 15;
            Bs[k][n4] = *(const float4*)&B[(size_t)(k0 + k) * ldb + bn + n4 * 4];
        }
        __syncthreads();
        #pragma unroll
        for (int k = 0; k < 16; k++) {
            const u64* Ap = (const u64*)&Asf[k * 64 + ty * 8];  // 4 m-pairs
            u64 a0 = Ap[0], a1 = Ap[1], a2 = Ap[2], a3 = Ap[3];
            float4 b = Bs[k][tx];
            u64 b0 = pack2(b.x, b.x), b1 = pack2(b.y, b.y);
            u64 b2 = pack2(b.z, b.z), b3 = pack2(b.w, b.w);
            ffma2(acc[0][0], a0, b0); ffma2(acc[0][1], a0, b1);
            ffma2(acc[0][2], a0, b2); ffma2(acc[0][3], a0, b3);
            ffma2(acc[1][0], a1, b0); ffma2(acc[1][1], a1, b1);
            ffma2(acc[1][2], a1, b2); ffma2(acc[1][3], a1, b3);
            ffma2(acc[2][0], a2, b0); ffma2(acc[2][1], a2, b1);
            ffma2(acc[2][2], a2, b2); ffma2(acc[2][3], a2, b3);
            ffma2(acc[3][0], a3, b0); ffma2(acc[3][1], a3, b1);
            ffma2(acc[3][2], a3, b2); ffma2(acc[3][3], a3, b3);
        }
        __syncthreads();
    }
}

__device__ __forceinline__ void unpack_acc64(u64 acc[4][4], float cr[8][4]) {
    #pragma unroll
    for (int i2 = 0; i2 < 4; i2++)
        #pragma unroll
        for (int j = 0; j < 4; j++) {
            float2 p = unpack2(acc[i2][j]);
            cr[2 * i2][j] = p.x;
            cr[2 * i2 + 1][j] = p.y;
        }
}

// Generic GEMM: C = act( A@B (+bias) ), batched over gridDim.z
template<int ACT, int BETA>
__global__ void __launch_bounds__(128)
sgemm64(const float* __restrict__ A, const float* __restrict__ B,
        const float* __restrict__ bias, float* __restrict__ C,
        int K, int lda, int ldb, int ldc,
        size_t sA, size_t sB, size_t sBias, size_t sC)
{
    __shared__ float4 As[16][16];
    __shared__ float4 Bs[16][16];
    const int z = blockIdx.z;
    A += (size_t)z * sA; B += (size_t)z * sB; C += (size_t)z * sC;
    const float* biasz = bias ? bias + (size_t)z * sBias : nullptr;
    const int bm = blockIdx.y * 64, bn = blockIdx.x * 64;
    const int tx = threadIdx.x & 15, ty = threadIdx.x >> 4;

    u64 acc[4][4] = {};
    mainloop64(A, B, K, lda, ldb, bm, bn, As, Bs, acc);
    float cr[8][4];
    unpack_acc64(acc, cr);

    const int n = bn + tx * 4;
    float4 bb = make_float4(0.f, 0.f, 0.f, 0.f);
    if (biasz) bb = *(const float4*)&biasz[n];
    #pragma unroll
    for (int i = 0; i < 8; i++) {
        int m = bm + ty * 8 + i;
        float4 r = make_float4(cr[i][0], cr[i][1], cr[i][2], cr[i][3]);
        if (BETA) {
            float4 c = *(const float4*)&C[(size_t)m * ldc + n];
            r.x += c.x; r.y += c.y; r.z += c.z; r.w += c.w;
        }
        r.x = activate<ACT>(r.x + bb.x);
        r.y = activate<ACT>(r.y + bb.y);
        r.z = activate<ACT>(r.z + bb.z);
        r.w = activate<ACT>(r.w + bb.w);
        *(float4*)&C[(size_t)m * ldc + n] = r;
    }
}

// GRU z/r fused: val = sigmoid(Cin[z] + A@B[z]).
// z==0: TZ = val.   z==1: RH = val * h.
__global__ void __launch_bounds__(128)
sgemm64_zr(const float* __restrict__ A, const float* __restrict__ B,
           const float* __restrict__ Cin, const float* __restrict__ h,
           float* __restrict__ TZ, float* __restrict__ RH, int K, int lda)
{
    __shared__ float4 As[16][16];
    __shared__ float4 Bs[16][16];
    const int z = blockIdx.z;
    const float* Bz = B + (size_t)z * 256 * 256;
    const float* Ci = Cin + (size_t)z * SZ_HD;
    const int bm = blockIdx.y * 64, bn = blockIdx.x * 64;
    const int tx = threadIdx.x & 15, ty = threadIdx.x >> 4;

    u64 acc[4][4] = {};
    mainloop64(A, Bz, K, lda, 256, bm, bn, As, Bs, acc);
    float cr[8][4];
    unpack_acc64(acc, cr);

    const int n = bn + tx * 4;
    #pragma unroll
    for (int i = 0; i < 8; i++) {
        int m = bm + ty * 8 + i;
        float4 c = *(const float4*)&Ci[(size_t)m * 256 + n];
        float4 r;
        r.x = activate<2>(cr[i][0] + c.x);
        r.y = activate<2>(cr[i][1] + c.y);
        r.z = activate<2>(cr[i][2] + c.z);
        r.w = activate<2>(cr[i][3] + c.w);
        if (z == 0) {
            *(float4*)&TZ[(size_t)m * 256 + n] = r;
        } else {
            float4 hh = *(const float4*)&h[(size_t)m * 256 + n];
            r.x *= hh.x; r.y *= hh.y; r.z *= hh.z; r.w *= hh.w;
            *(float4*)&RH[(size_t)m * 256 + n] = r;
        }
    }
}

// GRU candidate fused: ht = tanh(TH + A@B); h_out = TZ*h + (1-TZ)*ht;
// optionally dual-write h_out into out2 (ld 512).
__global__ void __launch_bounds__(128)
sgemm64_cand(const float* __restrict__ A, const float* __restrict__ B,
             const float* __restrict__ TH, const float* __restrict__ TZ,
             const float* __restrict__ h, float* __restrict__ h_out,
             float* __restrict__ out2, int K, int lda)
{
    __shared__ float4 As[16][16];
    __shared__ float4 Bs[16][16];
    const int bm = blockIdx.y * 64, bn = blockIdx.x * 64;
    const int tx = threadIdx.x & 15, ty = threadIdx.x >> 4;

    u64 acc[4][4] = {};
    mainloop64(A, B, K, lda, 256, bm, bn, As, Bs, acc);
    float cr[8][4];
    unpack_acc64(acc, cr);

    const int n = bn + tx * 4;
    #pragma unroll
    for (int i = 0; i < 8; i++) {
        int m = bm + ty * 8 + i;
        float4 th = *(const float4*)&TH[(size_t)m * 256 + n];
        float4 zg = *(const float4*)&TZ[(size_t)m * 256 + n];
        float4 hh = *(const float4*)&h[(size_t)m * 256 + n];
        float4 r;
        r.x = zg.x * hh.x + (1.f - zg.x) * tanhf(cr[i][0] + th.x);
        r.y = zg.y * hh.y + (1.f - zg.y) * tanhf(cr[i][1] + th.y);
        r.z = zg.z * hh.z + (1.f - zg.z) * tanhf(cr[i][2] + th.z);
        r.w = zg.w * hh.w + (1.f - zg.w) * tanhf(cr[i][3] + th.w);
        *(float4*)&h_out[(size_t)m * 256 + n] = r;
        if (out2) *(float4*)&out2[(size_t)m * 512 + n] = r;
    }
}

// 64x32x16 variant for ZD=32 GEMMs (128 threads, 4x4 micro-tile, FFMA2)
template<int ACT>
__global__ void __launch_bounds__(128)
sgemm32(const float* __restrict__ A, const float* __restrict__ B,
        const float* __restrict__ bias, float* __restrict__ C,
        int K, int lda,
        size_t sA, size_t sB, size_t sBias, size_t sC)
{
    __shared__ float4 As[16][16];
    __shared__ float4 Bs[16][8];
    const int z = blockIdx.z;
    A += (size_t)z * sA; B += (size_t)z * sB; C += (size_t)z * sC;
    const float* biasz = bias ? bias + (size_t)z * sBias : nullptr;

    const int tid = threadIdx.x;
    const int bm = blockIdx.y * 64;
    const int tx = tid & 7;     // n: tx*4
    const int ty = tid >> 3;    // m: ty*4

    u64 acc[2][4] = {};  // 2 m-pairs x 4 n
    float* Asf = (float*)As;

    for (int k0 = 0; k0 < K; k0 += 16) {
        #pragma unroll
        for (int it = 0; it < 2; it++) {
            int idx = tid + it * 128;
            int m = idx >> 2, c4 = idx & 3;
            float4 v = *(const float4*)&A[(size_t)(bm + m) * lda + k0 + c4 * 4];
            Asf[(c4 * 4 + 0) * 64 + m] = v.x;
            Asf[(c4 * 4 + 1) * 64 + m] = v.y;
            Asf[(c4 * 4 + 2) * 64 + m] = v.z;
            Asf[(c4 * 4 + 3) * 64 + m] = v.w;
        }
        {
            int k = tid >> 3, n4 = tid & 7;
            Bs[k][n4] = *(const float4*)&B[(size_t)(k0 + k) * 32 + n4 * 4];
        }
        __syncthreads();
        #pragma unroll
        for (int k = 0; k < 16; k++) {
            const u64* Ap = (const u64*)&Asf[k * 64 + ty * 4];
            u64 a0 = Ap[0], a1 = Ap[1];
            float4 b = Bs[k][tx];
            u64 b0 = pack2(b.x, b.x), b1 = pack2(b.y, b.y);
            u64 b2 = pack2(b.z, b.z), b3 = pack2(b.w, b.w);
            ffma2(acc[0][0], a0, b0); ffma2(acc[0][1], a0, b1);
            ffma2(acc[0][2], a0, b2); ffma2(acc[0][3], a0, b3);
            ffma2(acc[1][0], a1, b0); ffma2(acc[1][1], a1, b1);
            ffma2(acc[1][2], a1, b2); ffma2(acc[1][3], a1, b3);
        }
        __syncthreads();
    }

    float cr[4][4];
    #pragma unroll
    for (int i2 = 0; i2 < 2; i2++)
        #pragma unroll
        for (int j = 0; j < 4; j++) {
            float2 p = unpack2(acc[i2][j]);
            cr[2 * i2][j] = p.x; cr[2 * i2 + 1][j] = p.y;
        }

    const int n = tx * 4;
    float4 bb = make_float4(0.f, 0.f, 0.f, 0.f);
    if (biasz) bb = *(const float4*)&biasz[n];
    #pragma unroll
    for (int i = 0; i < 4; i++) {
        int m = bm + ty * 4 + i;
        float4 r = make_float4(cr[i][0] + bb.x, cr[i][1] + bb.y,
                               cr[i][2] + bb.z, cr[i][3] + bb.w);
        r.x = activate<ACT>(r.x); r.y = activate<ACT>(r.y);
        r.z = activate<ACT>(r.z); r.w = activate<ACT>(r.w);
        *(float4*)&C[(size_t)m * 32 + n] = r;
    }
}

// ---------------------------------------------------------------------------
// CSR build
// ---------------------------------------------------------------------------
__global__ void zero_csr_kernel() {
    int i = blockIdx.x * blockDim.x + threadIdx.x;
    if (i < Nn) { d_deg[i] = 0; d_cursor[i] = 0; }
}
__global__ void hist_kernel(const int* __restrict__ dst) {
    int i = blockIdx.x * blockDim.x + threadIdx.x;
    if (i < Ee) atomicAdd(&d_deg[dst[i]], 1);
}
__global__ void scan_kernel() {
    __shared__ int s0[2048], s1[2048];
    int t = threadIdx.x;  // 1024 threads
    s0[t] = d_deg[t]; s0[t + 1024] = d_deg[t + 1024];
    __syncthreads();
    int* cur = s0; int* nxt = s1;
    for (int off = 1; off < 2048; off <<= 1) {
        int i0 = t, i1 = t + 1024;
        nxt[i0] = cur[i0] + (i0 >= off ? cur[i0 - off] : 0);
        nxt[i1] = cur[i1] + (i1 >= off ? cur[i1 - off] : 0);
        __syncthreads();
        int* tmp = cur; cur = nxt; nxt = tmp;
    }
    d_rowptr[t + 1]    = cur[t];
    d_rowptr[t + 1025] = cur[t + 1024];
    if (t == 0) d_rowptr[0] = 0;
    float f0 = (float)(d_deg[t] + 1);
    float f1 = (float)(d_deg[t + 1024] + 1);
    d_degf[t] = f0;          d_dinv[t] = rsqrtf(f0);
    d_degf[t + 1024] = f1;   d_dinv[t + 1024] = rsqrtf(f1);
}
__global__ void fill_kernel(const int* __restrict__ src, const int* __restrict__ dst) {
    int i = blockIdx.x * blockDim.x + threadIdx.x;
    if (i < Ee) {
        int d = dst[i];
        int pos = atomicAdd(&d_cursor[d], 1);
        d_csrsrc[d_rowptr[d] + pos] = src[i];
    }
}

// ---------------------------------------------------------------------------
// Graph gathers
// ---------------------------------------------------------------------------
__global__ void gin_kernel(const float4* __restrict__ x, float4* __restrict__ out,
                           int D4, int npb)
{
    int lane = threadIdx.x % D4;
    int n = blockIdx.x * npb + threadIdx.x / D4;
    int beg = d_rowptr[n], end = d_rowptr[n + 1];
    float4 acc = x[(size_t)n * D4 + lane];
    for (int e = beg; e < end; e++) {
        float4 v = x[(size_t)d_csrsrc[e] * D4 + lane];
        acc.x += v.x; acc.y += v.y; acc.z += v.z; acc.w += v.w;
    }
    out[(size_t)n * D4 + lane] = acc;
}

// GCN (32-wide), batched z via blockIdx.y
__global__ void gcn_kernel(const float4* __restrict__ xw, float4* __restrict__ out,
                           const float4* __restrict__ bias)
{
    int z = blockIdx.y;
    xw  += (size_t)z * (SZ_ZD / 4);
    out += (size_t)z * (SZ_ZD / 4);
    bias += (size_t)z * 8;
    int lane = threadIdx.x & 7;
    int n = blockIdx.x * 16 + (threadIdx.x >> 3);
    int beg = d_rowptr[n], end = d_rowptr[n + 1];
    float4 acc = make_float4(0.f, 0.f, 0.f, 0.f);
    for (int e = beg; e < end; e++) {
        int s = d_csrsrc[e];
        float w = d_dinv[s];
        float4 v = xw[(size_t)s * 8 + lane];
        acc.x += w * v.x; acc.y += w * v.y; acc.z += w * v.z; acc.w += w * v.w;
    }
    float dn = d_dinv[n], id = 1.f / d_degf[n];
    float4 xn = xw[(size_t)n * 8 + lane];
    float4 b = bias[lane];
    out[(size_t)n * 8 + lane] = make_float4(
        dn * acc.x + id * xn.x + b.x, dn * acc.y + id * xn.y + b.y,
        dn * acc.z + id * xn.z + b.z, dn * acc.w + id * xn.w + b.w);
}

// std path (32-wide), batched z via blockIdx.y
__global__ void stdsp_kernel(const float4* __restrict__ tmp, float4* __restrict__ out,
                             const float4* __restrict__ bias)
{
    int z = blockIdx.y;
    tmp += (size_t)z * (SZ_ZD / 4);
    out += (size_t)z * (SZ_ZD / 4);
    bias += (size_t)z * 8;
    int lane = threadIdx.x & 7;
    int n = blockIdx.x * 16 + (threadIdx.x >> 3);
    int beg = d_rowptr[n], end = d_rowptr[n + 1];
    float4 acc = tmp[(size_t)n * 8 + lane];
    for (int e = beg; e < end; e++) {
        float4 v = tmp[(size_t)d_csrsrc[e] * 8 + lane];
        acc.x += v.x; acc.y += v.y; acc.z += v.z; acc.w += v.w;
    }
    float4 b = bias[lane];
    out[(size_t)n * 8 + lane] = make_float4(
        activate<4>(acc.x + b.x), activate<4>(acc.y + b.y),
        activate<4>(acc.z + b.z), activate<4>(acc.w + b.w));
}

// ---------------------------------------------------------------------------
// Elementwise
// ---------------------------------------------------------------------------
__global__ void z_kernel(const float* __restrict__ ms, const float* __restrict__ ss,
                         const float* __restrict__ es, const float* __restrict__ md,
                         const float* __restrict__ sd, const float* __restrict__ ed,
                         float* __restrict__ zs, float* __restrict__ zd,
                         float* __restrict__ zcat)
{
    int i = blockIdx.x * blockDim.x + threadIdx.x;
    if (i < Nn * ZD) {
        int n = i >> 5, j = i & 31;
        float a = ms[i] + ss[i] * es[i];
        float b = md[i] + sd[i] * ed[i];
        zs[i] = a; zd[i] = b;
        zcat[(size_t)n * 64 + j] = a;
        zcat[(size_t)n * 64 + 32 + j] = b;
    }
}

__global__ void init_kernel() {
    size_t i = (size_t)blockIdx.x * blockDim.x + threadIdx.x;
    if (i < SZ_2HD)    g_f[O_CAT + i] = 0.f;   // CAT (incl. h0 slot at cols 256..511)
    if (i < 2 * SZ_HD) g_f[O_H + i] = 0.f;     // h buffer 0, both layers
    if (i < 6) d_acc[i] = 0.0;
}

// ---------------------------------------------------------------------------
// Decoder (z_s @ z_d^T) fused with BCE partial sums (FFMA2, transposed smem)
// Row stride 66 floats (even) keeps all u64 shared reads 8B-aligned.
// ---------------------------------------------------------------------------
__global__ void __launch_bounds__(256)
dec_bce_kernel(const float* __restrict__ zs, const float* __restrict__ zd,
               const float* __restrict__ adj, float* __restrict__ dec)
{
    __shared__ float SsT[32][66];   // [k][m], stride 66 (8B-aligned pairs)
    __shared__ float SdT[32][66];   // [k][n]
    int tid = threadIdx.x;
    int bi = blockIdx.y * 64, bj = blockIdx.x * 64;
    for (int i = tid; i < 64 * 32; i += 256) {
        int r = i >> 5, c = i & 31;
        SsT[c][r] = zs[(size_t)(bi + r) * 32 + c];
        SdT[c][r] = zd[(size_t)(bj + r) * 32 + c];
    }
    __syncthreads();
    int tx = tid % 16, ty = tid / 16;
    u64 acc[2][4] = {};  // m-pairs x n
    #pragma unroll
    for (int k = 0; k < 32; k++) {
        const u64* Ap = (const u64*)&SsT[k][ty * 4];
        u64 a0 = Ap[0], a1 = Ap[1];
        const float* bp = &SdT[k][tx * 4];
        u64 b0 = pack2(bp[0], bp[0]), b1 = pack2(bp[1], bp[1]);
        u64 b2 = pack2(bp[2], bp[2]), b3 = pack2(bp[3], bp[3]);
        ffma2(acc[0][0], a0, b0); ffma2(acc[0][1], a0, b1);
        ffma2(acc[0][2], a0, b2); ffma2(acc[0][3], a0, b3);
        ffma2(acc[1][0], a1, b0); ffma2(acc[1][1], a1, b1);
        ffma2(acc[1][2], a1, b2); ffma2(acc[1][3], a1, b3);
    }
    float cr[4][4];
    #pragma unroll
    for (int i2 = 0; i2 < 2; i2++)
        #pragma unroll
        for (int j = 0; j < 4; j++) {
            float2 p = unpack2(acc[i2][j]);
            cr[2 * i2][j] = p.x; cr[2 * i2 + 1][j] = p.y;
        }
    float sa = 0.f, s1 = 0.f, s2 = 0.f;
    #pragma unroll
    for (int i = 0; i < 4; i++) {
        int r = bi + ty * 4 + i;
        #pragma unroll
        for (int j = 0; j < 4; j++) {
            int c = bj + tx * 4 + j;
            float d = cr[i][j];
            dec[(size_t)r * Nn + c] = d;
            float a = adj[(size_t)r * Nn + c];
            float lg = log1pf(expf(-fabsf(d)));
            float lsp = fminf(d, 0.f) - lg;
            float lsn = fminf(-d, 0.f) - lg;
            sa += a; s1 += a * lsp; s2 += (1.f - a) * lsn;
        }
    }
    block_add(&d_acc[0], sa);
    block_add(&d_acc[1], s1);
    block_add(&d_acc[2], s2);
}

// ---------------------------------------------------------------------------
// KLD + per-step finalize
// ---------------------------------------------------------------------------
__device__ __forceinline__ float kterm(float m1, float s1, float m2, float s2) {
    float a = s1 + 1e-10f, b = s2 + 1e-10f;
    float dm = m1 - m2;
    return 2.f * (logf(b) - logf(a)) + (a * a + dm * dm) / (b * b) - 1.f;
}

__global__ void kld_kernel(const float* __restrict__ ms, const float* __restrict__ ss,
                           const float* __restrict__ pm, const float* __restrict__ ps,
                           const float* __restrict__ md, const float* __restrict__ sd,
                           const float* __restrict__ pmd, const float* __restrict__ psd)
{
    int i = blockIdx.x * blockDim.x + threadIdx.x;
    float v = 0.f;
    if (i < Nn * ZD)
        v = kterm(ms[i], ss[i], pm[i], ps[i]) + kterm(md[i], sd[i], pmd[i], psd[i]);
    block_add(&d_acc[3], v);
}

__global__ void finalize_kernel(float* __restrict__ out) {
    double ssum = d_acc[0], S1 = d_acc[1], S2 = d_acc[2], K = d_acc[3];
    double nn2 = (double)Nn * (double)Nn;
    double posw = (nn2 - ssum) / ssum;
    double nrm  = nn2 / ((nn2 - ssum) * 2.0);
    double nll  = nrm * ((-posw) * S1 - S2) / nn2;
    double kld  = 0.5 * K / nn2;
    d_acc[4] += kld;
    d_acc[5] += nll;
    out[0] = (float)d_acc[4];
    out[1] = (float)d_acc[5];
    d_acc[0] = 0.0; d_acc[1] = 0.0; d_acc[2] = 0.0; d_acc[3] = 0.0;
}

// ---------------------------------------------------------------------------
// Host launch helpers
// ---------------------------------------------------------------------------
static inline void g64(const float* A, const float* B, const float* bias, float* C,
                       int Ncol, int K, int lda, int ldb, int ldc, int act, int beta,
                       int z, size_t sA, size_t sB, size_t sBias, size_t sC)
{
    dim3 g(Ncol / 64, Nn / 64, z);
    if (beta == 0) {
        if (act == 0)      sgemm64<0, 0><<<g, 128>>>(A, B, bias, C, K, lda, ldb, ldc, sA, sB, sBias, sC);
        else if (act == 1) sgemm64<1, 0><<<g, 128>>>(A, B, bias, C, K, lda, ldb, ldc, sA, sB, sBias, sC);
    }
}

static inline void g32(const float* A, const float* B, const float* bias, float* C,
                       int K, int lda, int act,
                       int z, size_t sA, size_t sB, size_t sBias, size_t sC)
{
    dim3 g(1, Nn / 64, z);
    if (act == 0)      sgemm32<0><<<g, 128>>>(A, B, bias, C, K, lda, sA, sB, sBias, sC);
    else if (act == 4) sgemm32<4><<<g, 128>>>(A, B, bias, C, K, lda, sA, sB, sBias, sC);
}

extern "C" void kernel_launch(void* const* d_in, const int* /*in_sizes*/, int /*n_in*/,
                              void* d_out, int /*out_size*/)
{
    const float* x       = (const float*)d_in[0];
    const int*   ei      = (const int*)  d_in[1];
    const float* adj     = (const float*)d_in[2];
    const float* eps_s   = (const float*)d_in[3];
    const float* eps_d   = (const float*)d_in[4];
    const float* phi_x_w = (const float*)d_in[5];
    const float* phi_z_w = (const float*)d_in[6];
    const float* gxw0    = (const float*)d_in[7];   // [3,512,256]
    const float* gxw1    = (const float*)d_in[8];   // [3,256,256]
    const float* ghw     = (const float*)d_in[9];   // [2,3,256,256]
    const float* enc_w   = (const float*)d_in[10];  // [2,512,256]
    const float* enc_b   = (const float*)d_in[11];
    const float* mean_w  = (const float*)d_in[12];  // [2,256,32]
    const float* mean_b  = (const float*)d_in[13];
    const float* std_w   = (const float*)d_in[14];
    const float* std_b   = (const float*)d_in[15];
    const float* pri_w   = (const float*)d_in[16];  // [2,256,256]
    const float* pri_b   = (const float*)d_in[17];
    const float* pri_mw  = (const float*)d_in[18];
    const float* pri_mb  = (const float*)d_in[19];
    const float* pri_sw  = (const float*)d_in[20];
    const float* pri_sb  = (const float*)d_in[21];
    float* out = (float*)d_out;
    float* dec_out = out + 2;  // [T, N, N]

    float* F = nullptr;
    cudaGetSymbolAddress((void**)&F, g_f);

    float* CAT    = F + O_CAT;     // == GIN: [phi_x | h_last], later [phi_x | phi_z]
    float* CATP   = F + O_CATP;
    float* ENC_S  = F + O_ENC_S;
    float* XW_S   = F + O_XW_S;
    float* MEAN_S = F + O_MEAN_S;
    float* MEAN_D = F + O_MEAN_D;
    float* STMP_S = F + O_STMP_S;
    float* STD_S  = F + O_STD_S;
    float* STD_D  = F + O_STD_D;
    float* PRI_S  = F + O_PRI_S;
    float* PM_S   = F + O_PM_S;
    float* PS_S   = F + O_PS_S;
    float* PM_D   = F + O_PM_D;
    float* PS_D   = F + O_PS_D;
    float* Z_S    = F + O_Z_S;
    float* Z_D    = F + O_Z_D;
    float* ZCAT   = F + O_ZCAT;
    float* GPRE   = F + O_GPRE;
    float* HPRE   = F + O_HPRE;
    float* XPRE1  = F + O_XPRE1;
    float* TZ     = F + O_TZ;
    float* TH     = F + O_TH;
    float* RH     = F + O_RH;
    float* RHP    = F + O_RHP;

    init_kernel<<<(SZ_2HD + 255) / 256, 256>>>();

    for (int t = 0; t < Tt; t++) {
        const float* x_t   = x + (size_t)t * Nn * XD;
        const int*   src_t = ei + (size_t)t * 2 * Ee;
        const int*   dst_t = src_t + Ee;
        const float* adj_t = adj + (size_t)t * Nn * Nn;
        const float* es_t  = eps_s + (size_t)t * SZ_ZD;
        const float* ed_t  = eps_d + (size_t)t * SZ_ZD;
        float* Hc = F + O_H + (size_t)(t & 1) * 2 * SZ_HD;
        float* Hn = F + O_H + (size_t)((t + 1) & 1) * 2 * SZ_HD;
        float* hlast = Hc + SZ_HD;
        float* dec_t = dec_out + (size_t)t * Nn * Nn;

        // --- CSR for this timestep ---
        zero_csr_kernel<<<(Nn + 255) / 256, 256>>>();
        hist_kernel<<<Ee / 256, 256>>>(dst_t);
        scan_kernel<<<1, 1024>>>();
        fill_kernel<<<Ee / 256, 256>>>(src_t, dst_t);

        // --- phi_x into CAT[:,0:256]; CAT[:,256:512] already holds h_last
        //     (written by previous step's fused GRU epilogue; zeros at t=0) ---
        g64(x_t, phi_x_w, nullptr, CAT, 256, XD, XD, 256, 512, 1, 0, 1, 0, 0, 0, 0);

        // --- cat_pre = gin(cat) ---
        gin_kernel<<<Nn, 128>>>((const float4*)CAT, (float4*)CATP, 128, 1);

        // --- encoders (batched z=2) ---
        g64(CATP, enc_w, enc_b, ENC_S, 256, 512, 512, 256, 256, 1, 0,
            2, 0, 512 * 256, 256, SZ_HD);

        // --- mean/std temporaries (batched z=2 each) ---
        g32(ENC_S, mean_w, nullptr, XW_S, 256, 256, 0, 2, SZ_HD, 256 * 32, 0, SZ_ZD);
        g32(ENC_S, std_w,  nullptr, STMP_S, 256, 256, 0, 2, SZ_HD, 256 * 32, 0, SZ_ZD);
        gcn_kernel<<<dim3(Nn / 16, 2), 128>>>((const float4*)XW_S, (float4*)MEAN_S,
                                              (const float4*)mean_b);
        stdsp_kernel<<<dim3(Nn / 16, 2), 128>>>((const float4*)STMP_S, (float4*)STD_S,
                                                (const float4*)std_b);

        // --- priors (batched) ---
        g64(hlast, pri_w, pri_b, PRI_S, 256, 256, 256, 256, 256, 1, 0,
            2, 0, 256 * 256, 256, SZ_HD);
        g32(PRI_S, pri_mw, pri_mb, PM_S, 256, 256, 0, 2, SZ_HD, 256 * 32, 32, 2 * SZ_ZD);
        g32(PRI_S, pri_sw, pri_sb, PS_S, 256, 256, 4, 2, SZ_HD, 256 * 32, 32, 2 * SZ_ZD);

        // --- reparameterize; phi_z straight into CAT[:,256:512] (h copy dead) ---
        z_kernel<<<(Nn * ZD + 255) / 256, 256>>>(MEAN_S, STD_S, es_t,
                                                 MEAN_D, STD_D, ed_t,
                                                 Z_S, Z_D, ZCAT);
        g64(ZCAT, phi_z_w, nullptr, CAT + 256, 256, 64, 64, 256, 512, 1, 0,
            1, 0, 0, 0, 0);

        // --- decoder + fused BCE sums ---
        dec_bce_kernel<<<dim3(Nn / 64, Nn / 64), 256>>>(Z_S, Z_D, adj_t, dec_t);

        // --- KLD + per-step finalize ---
        kld_kernel<<<(Nn * ZD + 255) / 256, 256>>>(MEAN_S, STD_S, PM_S, PS_S,
                                                   MEAN_D, STD_D, PM_D, PS_D);
        finalize_kernel<<<1, 1>>>(out);

        // --- graph-GRU, 2 layers ---
        for (int l = 0; l < 2; l++) {
            const float* xi  = (l == 0) ? CAT : Hn;      // l1 input = new_h[0]
            float* xpre      = (l == 0) ? GPRE : XPRE1;
            int Kx           = (l == 0) ? 512 : 256;
            const float* xw  = (l == 0) ? gxw0 : gxw1;
            const float* hw  = ghw + (size_t)l * 3 * 256 * 256;
            float* h_l       = Hc + (size_t)l * SZ_HD;
            float* h_out     = Hn + (size_t)l * SZ_HD;
            // layer 1's fused epilogue also stores next step's h_last into CAT
            float* out2      = (l == 1) ? (CAT + 256) : nullptr;

            if (l == 0)
                gin_kernel<<<Nn, 128>>>((const float4*)xi, (float4*)xpre, 128, 1);
            else
                gin_kernel<<<Nn / 2, 128>>>((const float4*)xi, (float4*)xpre, 64, 2);
            gin_kernel<<<Nn / 2, 128>>>((const float4*)h_l, (float4*)HPRE, 64, 2);

            // x-side of all 3 gates, batched z=3 -> TZ|TR|TH
            g64(xpre, xw, nullptr, TZ, 256, Kx, Kx, 256, 256, 0, 0,
                3, 0, (size_t)Kx * 256, 0, SZ_HD);
            // h-side z,r gates fused: TZ = sigmoid(TZ + HPRE@hw_z);
            //                         RH = sigmoid(TR + HPRE@hw_r) * h_l
            sgemm64_zr<<<dim3(4, Nn / 64, 2), 128>>>(HPRE, hw, TZ, h_l, TZ, RH, 256, 256);
            // candidate: gin(RH) then fused tanh + new-h blend
            gin_kernel<<<Nn / 2, 128>>>((const float4*)RH, (float4*)RHP, 64, 2);
            sgemm64_cand<<<dim3(4, Nn / 64), 128>>>(RHP, hw + 2 * 256 * 256,
                                                    TH, TZ, h_l, h_out, out2, 256, 256);
        }
    }
}

// round 8
// speedup vs baseline: 2.2151x; 1.1026x over previous
#include <cuda_runtime.h>
#include <cstdint>
#include <cstddef>

// ---------------------------------------------------------------------------
// Problem constants
// ---------------------------------------------------------------------------
#define Nn 2048
#define Ee 32768
#define Tt 12
#define XD 128
#define HD 256
#define ZD 32

constexpr size_t SZ_HD  = (size_t)Nn * HD;      // 524288
constexpr size_t SZ_2HD = (size_t)Nn * 2 * HD;  // 1048576
constexpr size_t SZ_ZD  = (size_t)Nn * ZD;      // 65536

// ---------------------------------------------------------------------------
// Scratch layout (adjacency is load-bearing for batched/grouped GEMMs)
// ---------------------------------------------------------------------------
constexpr size_t O_CAT   = 0;                    // [N,512]  (phi_x | h1/phi_z)
constexpr size_t O_CATP  = O_CAT   + SZ_2HD;     // gin(cat)
constexpr size_t O_ENC_S = O_CATP  + SZ_2HD;
constexpr size_t O_ENC_D = O_ENC_S + SZ_HD;
constexpr size_t O_XW_S  = O_ENC_D + SZ_HD;
constexpr size_t O_XW_D  = O_XW_S  + SZ_ZD;
constexpr size_t O_MEAN_S= O_XW_D  + SZ_ZD;
constexpr size_t O_MEAN_D= O_MEAN_S+ SZ_ZD;
constexpr size_t O_STMP_S= O_MEAN_D+ SZ_ZD;
constexpr size_t O_STMP_D= O_STMP_S+ SZ_ZD;
constexpr size_t O_STD_S = O_STMP_D+ SZ_ZD;
constexpr size_t O_STD_D = O_STD_S + SZ_ZD;
constexpr size_t O_PRI_S = O_STD_D + SZ_ZD;
constexpr size_t O_PRI_D = O_PRI_S + SZ_HD;
constexpr size_t O_PM_S  = O_PRI_D + SZ_HD;      // PM_S|PS_S|PM_D|PS_D
constexpr size_t O_PS_S  = O_PM_S  + SZ_ZD;
constexpr size_t O_PM_D  = O_PS_S  + SZ_ZD;
constexpr size_t O_PS_D  = O_PM_D  + SZ_ZD;
constexpr size_t O_Z_S   = O_PS_D  + SZ_ZD;
constexpr size_t O_Z_D   = O_Z_S   + SZ_ZD;
constexpr size_t O_GPRE  = O_Z_D   + SZ_ZD;      // gin(g_in) [N,512]
constexpr size_t O_HPRE  = O_GPRE  + SZ_2HD;     // gin(h[i]) [N,256]
constexpr size_t O_XPRE1 = O_HPRE  + SZ_HD;      // gin(new_h0) [N,256]
constexpr size_t O_TZ    = O_XPRE1 + SZ_HD;
constexpr size_t O_TR    = O_TZ    + SZ_HD;
constexpr size_t O_TH    = O_TR    + SZ_HD;
constexpr size_t O_RH    = O_TH    + SZ_HD;
constexpr size_t O_RHP   = O_RH    + SZ_HD;
constexpr size_t O_H     = O_RHP   + SZ_HD;      // 2 dbl-buffers x NL layers
constexpr size_t TOTAL_F = O_H + 4 * SZ_HD;

__device__ __align__(256) float g_f[TOTAL_F];
__device__ int    d_rowptr[Nn + 1];
__device__ int    d_csrsrc[Ee];
__device__ float  d_degf[Nn];
__device__ float  d_dinv[Nn];
__device__ double d_acc[6];

// ---------------------------------------------------------------------------
// f32x2 packed-FMA helpers (Blackwell FFMA2 via PTX)
// ---------------------------------------------------------------------------
typedef unsigned long long u64;

__device__ __forceinline__ u64 pack2(float x, float y) {
    u64 r; asm("mov.b64 %0, {%1, %2};" : "=l"(r) : "f"(x), "f"(y)); return r;
}
__device__ __forceinline__ void ffma2(u64& c, u64 a, u64 b) {
    asm("fma.rn.f32x2 %0, %1, %2, %0;" : "+l"(c) : "l"(a), "l"(b));
}
__device__ __forceinline__ float2 unpack2(u64 v) {
    float2 r; asm("mov.b64 {%0, %1}, %2;" : "=f"(r.x), "=f"(r.y) : "l"(v)); return r;
}

// ---------------------------------------------------------------------------
// Activations / reductions
// ---------------------------------------------------------------------------
template<int ACT>
__device__ __forceinline__ float activate(float v) {
    if (ACT == 1) return fmaxf(v, 0.f);
    if (ACT == 2) return 1.f / (1.f + expf(-v));
    if (ACT == 3) return tanhf(v);
    if (ACT == 4) return fmaxf(v, 0.f) + log1pf(expf(-fabsf(v)));  // softplus
    return v;
}

__device__ __forceinline__ float softplusf(float v) {
    return fmaxf(v, 0.f) + log1pf(expf(-fabsf(v)));
}

__device__ __forceinline__ void block_add(double* target, float v) {
    #pragma unroll
    for (int o = 16; o; o >>= 1) v += __shfl_down_sync(0xffffffffu, v, o);
    __shared__ float wsum[32];
    int lane = threadIdx.x & 31, wid = threadIdx.x >> 5;
    if (lane == 0) wsum[wid] = v;
    __syncthreads();
    if (threadIdx.x == 0) {
        float s = 0.f;
        int nw = (blockDim.x + 31) >> 5;
        for (int i = 0; i < nw; i++) s += wsum[i];
        atomicAdd(target, (double)s);
    }
    __syncthreads();
}

// ---------------------------------------------------------------------------
// 64x64x16 FFMA2 mainloop (128 threads, 8x4 micro-tile).
// ---------------------------------------------------------------------------
__device__ __forceinline__ void mainloop64(
    const float* __restrict__ A, const float* __restrict__ B,
    int K, int lda, int ldb, int bm, int bn,
    float4 (*As)[16], float4 (*Bs)[16], u64 acc[4][4])
{
    const int tid = threadIdx.x;
    const int tx = tid & 15;
    const int ty = tid >> 4;
    float* Asf = (float*)As;

    for (int k0 = 0; k0 < K; k0 += 16) {
        #pragma unroll
        for (int it = 0; it < 2; it++) {
            int idx = tid + it * 128;
            int m = idx >> 2, c4 = idx & 3;
            float4 v = *(const float4*)&A[(size_t)(bm + m) * lda + k0 + c4 * 4];
            Asf[(c4 * 4 + 0) * 64 + m] = v.x;
            Asf[(c4 * 4 + 1) * 64 + m] = v.y;
            Asf[(c4 * 4 + 2) * 64 + m] = v.z;
            Asf[(c4 * 4 + 3) * 64 + m] = v.w;
        }
        #pragma unroll
        for (int it = 0; it < 2; it++) {
            int idx = tid + it * 128;
            int k = idx >> 4, n4 = idx & 15;
            Bs[k][n4] = *(const float4*)&B[(size_t)(k0 + k) * ldb + bn + n4 * 4];
        }
        __syncthreads();
        #pragma unroll
        for (int k = 0; k < 16; k++) {
            const u64* Ap = (const u64*)&Asf[k * 64 + ty * 8];
            u64 a0 = Ap[0], a1 = Ap[1], a2 = Ap[2], a3 = Ap[3];
            float4 b = Bs[k][tx];
            u64 b0 = pack2(b.x, b.x), b1 = pack2(b.y, b.y);
            u64 b2 = pack2(b.z, b.z), b3 = pack2(b.w, b.w);
            ffma2(acc[0][0], a0, b0); ffma2(acc[0][1], a0, b1);
            ffma2(acc[0][2], a0, b2); ffma2(acc[0][3], a0, b3);
            ffma2(acc[1][0], a1, b0); ffma2(acc[1][1], a1, b1);
            ffma2(acc[1][2], a1, b2); ffma2(acc[1][3], a1, b3);
            ffma2(acc[2][0], a2, b0); ffma2(acc[2][1], a2, b1);
            ffma2(acc[2][2], a2, b2); ffma2(acc[2][3], a2, b3);
            ffma2(acc[3][0], a3, b0); ffma2(acc[3][1], a3, b1);
            ffma2(acc[3][2], a3, b2); ffma2(acc[3][3], a3, b3);
        }
        __syncthreads();
    }
}

__device__ __forceinline__ void unpack_acc64(u64 acc[4][4], float cr[8][4]) {
    #pragma unroll
    for (int i2 = 0; i2 < 4; i2++)
        #pragma unroll
        for (int j = 0; j < 4; j++) {
            float2 p = unpack2(acc[i2][j]);
            cr[2 * i2][j] = p.x;
            cr[2 * i2 + 1][j] = p.y;
        }
}

// Generic GEMM: C = act( A@B (+bias) ), batched over gridDim.z
template<int ACT>
__global__ void __launch_bounds__(128)
sgemm64(const float* __restrict__ A, const float* __restrict__ B,
        const float* __restrict__ bias, float* __restrict__ C,
        int K, int lda, int ldb, int ldc,
        size_t sA, size_t sB, size_t sBias, size_t sC)
{
    __shared__ float4 As[16][16];
    __shared__ float4 Bs[16][16];
    const int z = blockIdx.z;
    A += (size_t)z * sA; B += (size_t)z * sB; C += (size_t)z * sC;
    const float* biasz = bias ? bias + (size_t)z * sBias : nullptr;
    const int bm = blockIdx.y * 64, bn = blockIdx.x * 64;
    const int tx = threadIdx.x & 15, ty = threadIdx.x >> 4;

    u64 acc[4][4] = {};
    mainloop64(A, B, K, lda, ldb, bm, bn, As, Bs, acc);
    float cr[8][4];
    unpack_acc64(acc, cr);

    const int n = bn + tx * 4;
    float4 bb = make_float4(0.f, 0.f, 0.f, 0.f);
    if (biasz) bb = *(const float4*)&biasz[n];
    #pragma unroll
    for (int i = 0; i < 8; i++) {
        int m = bm + ty * 8 + i;
        float4 r;
        r.x = activate<ACT>(cr[i][0] + bb.x);
        r.y = activate<ACT>(cr[i][1] + bb.y);
        r.z = activate<ACT>(cr[i][2] + bb.z);
        r.w = activate<ACT>(cr[i][3] + bb.w);
        *(float4*)&C[(size_t)m * ldc + n] = r;
    }
}

// Grouped encoders + priors: z0/z1 = enc_s/enc_d (K=512, A=CATP),
// z2/z3 = pri_s/pri_d (K=256, A=hlast). All relu+bias, ldc=256.
__global__ void __launch_bounds__(128)
encpri_kernel(const float* __restrict__ CATP, const float* __restrict__ hlast,
              const float* __restrict__ enc_w, const float* __restrict__ enc_b,
              const float* __restrict__ pri_w, const float* __restrict__ pri_b,
              float* __restrict__ ENC_S, float* __restrict__ PRI_S)
{
    __shared__ float4 As[16][16];
    __shared__ float4 Bs[16][16];
    const int z = blockIdx.z;
    const float* A; const float* B; const float* bias; float* C;
    int K, lda;
    if (z < 2) {
        A = CATP; K = 512; lda = 512;
        B = enc_w + (size_t)z * 512 * 256;
        bias = enc_b + (size_t)z * 256;
        C = ENC_S + (size_t)z * SZ_HD;
    } else {
        A = hlast; K = 256; lda = 256;
        B = pri_w + (size_t)(z - 2) * 256 * 256;
        bias = pri_b + (size_t)(z - 2) * 256;
        C = PRI_S + (size_t)(z - 2) * SZ_HD;
    }
    const int bm = blockIdx.y * 64, bn = blockIdx.x * 64;
    const int tx = threadIdx.x & 15, ty = threadIdx.x >> 4;

    u64 acc[4][4] = {};
    mainloop64(A, B, K, lda, 256, bm, bn, As, Bs, acc);
    float cr[8][4];
    unpack_acc64(acc, cr);

    const int n = bn + tx * 4;
    float4 bb = *(const float4*)&bias[n];
    #pragma unroll
    for (int i = 0; i < 8; i++) {
        int m = bm + ty * 8 + i;
        float4 r;
        r.x = fmaxf(cr[i][0] + bb.x, 0.f);
        r.y = fmaxf(cr[i][1] + bb.y, 0.f);
        r.z = fmaxf(cr[i][2] + bb.z, 0.f);
        r.w = fmaxf(cr[i][3] + bb.w, 0.f);
        *(float4*)&C[(size_t)m * 256 + n] = r;
    }
}

// GRU z/r fused: val = sigmoid(Cin[z] + A@B[z]).
// z==0: TZ = val.   z==1: RH = val * h.
__global__ void __launch_bounds__(128)
sgemm64_zr(const float* __restrict__ A, const float* __restrict__ B,
           const float* __restrict__ Cin, const float* __restrict__ h,
           float* __restrict__ TZ, float* __restrict__ RH, int K, int lda)
{
    __shared__ float4 As[16][16];
    __shared__ float4 Bs[16][16];
    const int z = blockIdx.z;
    const float* Bz = B + (size_t)z * 256 * 256;
    const float* Ci = Cin + (size_t)z * SZ_HD;
    const int bm = blockIdx.y * 64, bn = blockIdx.x * 64;
    const int tx = threadIdx.x & 15, ty = threadIdx.x >> 4;

    u64 acc[4][4] = {};
    mainloop64(A, Bz, K, lda, 256, bm, bn, As, Bs, acc);
    float cr[8][4];
    unpack_acc64(acc, cr);

    const int n = bn + tx * 4;
    #pragma unroll
    for (int i = 0; i < 8; i++) {
        int m = bm + ty * 8 + i;
        float4 c = *(const float4*)&Ci[(size_t)m * 256 + n];
        float4 r;
        r.x = activate<2>(cr[i][0] + c.x);
        r.y = activate<2>(cr[i][1] + c.y);
        r.z = activate<2>(cr[i][2] + c.z);
        r.w = activate<2>(cr[i][3] + c.w);
        if (z == 0) {
            *(float4*)&TZ[(size_t)m * 256 + n] = r;
        } else {
            float4 hh = *(const float4*)&h[(size_t)m * 256 + n];
            r.x *= hh.x; r.y *= hh.y; r.z *= hh.z; r.w *= hh.w;
            *(float4*)&RH[(size_t)m * 256 + n] = r;
        }
    }
}

// GRU candidate fused: ht = tanh(TH + A@B); h_out = TZ*h + (1-TZ)*ht;
// optionally dual-write h_out into out2 (ld 512).
__global__ void __launch_bounds__(128)
sgemm64_cand(const float* __restrict__ A, const float* __restrict__ B,
             const float* __restrict__ TH, const float* __restrict__ TZ,
             const float* __restrict__ h, float* __restrict__ h_out,
             float* __restrict__ out2, int K, int lda)
{
    __shared__ float4 As[16][16];
    __shared__ float4 Bs[16][16];
    const int bm = blockIdx.y * 64, bn = blockIdx.x * 64;
    const int tx = threadIdx.x & 15, ty = threadIdx.x >> 4;

    u64 acc[4][4] = {};
    mainloop64(A, B, K, lda, 256, bm, bn, As, Bs, acc);
    float cr[8][4];
    unpack_acc64(acc, cr);

    const int n = bn + tx * 4;
    #pragma unroll
    for (int i = 0; i < 8; i++) {
        int m = bm + ty * 8 + i;
        float4 th = *(const float4*)&TH[(size_t)m * 256 + n];
        float4 zg = *(const float4*)&TZ[(size_t)m * 256 + n];
        float4 hh = *(const float4*)&h[(size_t)m * 256 + n];
        float4 r;
        r.x = zg.x * hh.x + (1.f - zg.x) * tanhf(cr[i][0] + th.x);
        r.y = zg.y * hh.y + (1.f - zg.y) * tanhf(cr[i][1] + th.y);
        r.z = zg.z * hh.z + (1.f - zg.z) * tanhf(cr[i][2] + th.z);
        r.w = zg.w * hh.w + (1.f - zg.w) * tanhf(cr[i][3] + th.w);
        *(float4*)&h_out[(size_t)m * 256 + n] = r;
        if (out2) *(float4*)&out2[(size_t)m * 512 + n] = r;
    }
}

// phi_z GEMM with inline reparameterization:
// A[n, k<32]  = mean_s + std_s*eps_s;  A[n, k>=32] = mean_d + std_d*eps_d
// C = relu(A @ W) into CAT[:,256:512] (ld 512). Blocks with bn==0 also
// persist Z_S/Z_D for the decoder.
__global__ void __launch_bounds__(128)
phi_z_kernel(const float4* __restrict__ ms, const float4* __restrict__ ss,
             const float4* __restrict__ es, const float4* __restrict__ md,
             const float4* __restrict__ sd, const float4* __restrict__ ed,
             const float* __restrict__ W, float* __restrict__ C,
             float4* __restrict__ zs4, float4* __restrict__ zd4)
{
    __shared__ float4 As[16][16];
    __shared__ float4 Bs[16][16];
    const int tid = threadIdx.x;
    const int bm = blockIdx.y * 64, bn = blockIdx.x * 64;
    const int tx = tid & 15, ty = tid >> 4;
    float* Asf = (float*)As;

    u64 acc[4][4] = {};
    for (int k0 = 0; k0 < 64; k0 += 16) {
        #pragma unroll
        for (int it = 0; it < 2; it++) {
            int idx = tid + it * 128;
            int m = idx >> 2, c4 = idx & 3;
            int n = bm + m;
            int kk = k0 + c4 * 4;    // multiple of 4
            float4 v;
            if (kk < 32) {
                int j4 = kk >> 2;
                float4 a = ms[(size_t)n * 8 + j4];
                float4 s = ss[(size_t)n * 8 + j4];
                float4 e = es[(size_t)n * 8 + j4];
                v = make_float4(a.x + s.x * e.x, a.y + s.y * e.y,
                                a.z + s.z * e.z, a.w + s.w * e.w);
                if (blockIdx.x == 0) zs4[(size_t)n * 8 + j4] = v;
            } else {
                int j4 = (kk - 32) >> 2;
                float4 a = md[(size_t)n * 8 + j4];
                float4 s = sd[(size_t)n * 8 + j4];
                float4 e = ed[(size_t)n * 8 + j4];
                v = make_float4(a.x + s.x * e.x, a.y + s.y * e.y,
                                a.z + s.z * e.z, a.w + s.w * e.w);
                if (blockIdx.x == 0) zd4[(size_t)n * 8 + j4] = v;
            }
            Asf[(c4 * 4 + 0) * 64 + m] = v.x;
            Asf[(c4 * 4 + 1) * 64 + m] = v.y;
            Asf[(c4 * 4 + 2) * 64 + m] = v.z;
            Asf[(c4 * 4 + 3) * 64 + m] = v.w;
        }
        #pragma unroll
        for (int it = 0; it < 2; it++) {
            int idx = tid + it * 128;
            int k = idx >> 4, n4 = idx & 15;
            Bs[k][n4] = *(const float4*)&W[(size_t)(k0 + k) * 256 + bn + n4 * 4];
        }
        __syncthreads();
        #pragma unroll
        for (int k = 0; k < 16; k++) {
            const u64* Ap = (const u64*)&Asf[k * 64 + ty * 8];
            u64 a0 = Ap[0], a1 = Ap[1], a2 = Ap[2], a3 = Ap[3];
            float4 b = Bs[k][tx];
            u64 b0 = pack2(b.x, b.x), b1 = pack2(b.y, b.y);
            u64 b2 = pack2(b.z, b.z), b3 = pack2(b.w, b.w);
            ffma2(acc[0][0], a0, b0); ffma2(acc[0][1], a0, b1);
            ffma2(acc[0][2], a0, b2); ffma2(acc[0][3], a0, b3);
            ffma2(acc[1][0], a1, b0); ffma2(acc[1][1], a1, b1);
            ffma2(acc[1][2], a1, b2); ffma2(acc[1][3], a1, b3);
            ffma2(acc[2][0], a2, b0); ffma2(acc[2][1], a2, b1);
            ffma2(acc[2][2], a2, b2); ffma2(acc[2][3], a2, b3);
            ffma2(acc[3][0], a3, b0); ffma2(acc[3][1], a3, b1);
            ffma2(acc[3][2], a3, b2); ffma2(acc[3][3], a3, b3);
        }
        __syncthreads();
    }
    float cr[8][4];
    unpack_acc64(acc, cr);
    const int n = bn + tx * 4;
    #pragma unroll
    for (int i = 0; i < 8; i++) {
        int m = bm + ty * 8 + i;
        float4 r;
        r.x = fmaxf(cr[i][0], 0.f);
        r.y = fmaxf(cr[i][1], 0.f);
        r.z = fmaxf(cr[i][2], 0.f);
        r.w = fmaxf(cr[i][3], 0.f);
        *(float4*)&C[(size_t)m * 512 + n] = r;
    }
}

// Grouped 64x32x16 GEMMs: 8 jobs via blockIdx.z.
// z0/1: XW  = ENC_* @ mean_w[*]       (no bias, linear)
// z2/3: STMP= ENC_* @ std_w[*]        (no bias, linear)
// z4/6: PM  = PRI_* @ pri_mw[*] + b   (linear)
// z5/7: PS  = PRI_* @ pri_sw[*] + b   (softplus)
__global__ void __launch_bounds__(128)
g32_kernel(const float* __restrict__ ENC_S, const float* __restrict__ PRI_S,
           const float* __restrict__ mean_w, const float* __restrict__ std_w,
           const float* __restrict__ pri_mw, const float* __restrict__ pri_mb,
           const float* __restrict__ pri_sw, const float* __restrict__ pri_sb,
           float* __restrict__ XW_S, float* __restrict__ STMP_S,
           float* __restrict__ PM_S)
{
    __shared__ float4 As[16][16];
    __shared__ float4 Bs[16][8];
    const int z = blockIdx.z;
    const float* A; const float* B; const float* bias = nullptr; float* C;
    int act = 0;
    switch (z) {
        case 0: A = ENC_S;          B = mean_w;        C = XW_S;                break;
        case 1: A = ENC_S + SZ_HD;  B = mean_w + 8192; C = XW_S + SZ_ZD;        break;
        case 2: A = ENC_S;          B = std_w;         C = STMP_S;              break;
        case 3: A = ENC_S + SZ_HD;  B = std_w + 8192;  C = STMP_S + SZ_ZD;      break;
        case 4: A = PRI_S;          B = pri_mw;        C = PM_S;
                bias = pri_mb;                                                  break;
        case 5: A = PRI_S;          B = pri_sw;        C = PM_S + SZ_ZD;
                bias = pri_sb; act = 4;                                         break;
        case 6: A = PRI_S + SZ_HD;  B = pri_mw + 8192; C = PM_S + 2 * SZ_ZD;
                bias = pri_mb + 32;                                             break;
        default:A = PRI_S + SZ_HD;  B = pri_sw + 8192; C = PM_S + 3 * SZ_ZD;
                bias = pri_sb + 32; act = 4;                                    break;
    }

    const int tid = threadIdx.x;
    const int bm = blockIdx.y * 64;
    const int tx = tid & 7;
    const int ty = tid >> 3;

    u64 acc[2][4] = {};
    float* Asf = (float*)As;

    for (int k0 = 0; k0 < 256; k0 += 16) {
        #pragma unroll
        for (int it = 0; it < 2; it++) {
            int idx = tid + it * 128;
            int m = idx >> 2, c4 = idx & 3;
            float4 v = *(const float4*)&A[(size_t)(bm + m) * 256 + k0 + c4 * 4];
            Asf[(c4 * 4 + 0) * 64 + m] = v.x;
            Asf[(c4 * 4 + 1) * 64 + m] = v.y;
            Asf[(c4 * 4 + 2) * 64 + m] = v.z;
            Asf[(c4 * 4 + 3) * 64 + m] = v.w;
        }
        {
            int k = tid >> 3, n4 = tid & 7;
            Bs[k][n4] = *(const float4*)&B[(size_t)(k0 + k) * 32 + n4 * 4];
        }
        __syncthreads();
        #pragma unroll
        for (int k = 0; k < 16; k++) {
            const u64* Ap = (const u64*)&Asf[k * 64 + ty * 4];
            u64 a0 = Ap[0], a1 = Ap[1];
            float4 b = Bs[k][tx];
            u64 b0 = pack2(b.x, b.x), b1 = pack2(b.y, b.y);
            u64 b2 = pack2(b.z, b.z), b3 = pack2(b.w, b.w);
            ffma2(acc[0][0], a0, b0); ffma2(acc[0][1], a0, b1);
            ffma2(acc[0][2], a0, b2); ffma2(acc[0][3], a0, b3);
            ffma2(acc[1][0], a1, b0); ffma2(acc[1][1], a1, b1);
            ffma2(acc[1][2], a1, b2); ffma2(acc[1][3], a1, b3);
        }
        __syncthreads();
    }

    float cr[4][4];
    #pragma unroll
    for (int i2 = 0; i2 < 2; i2++)
        #pragma unroll
        for (int j = 0; j < 4; j++) {
            float2 p = unpack2(acc[i2][j]);
            cr[2 * i2][j] = p.x; cr[2 * i2 + 1][j] = p.y;
        }

    const int n = tx * 4;
    float4 bb = make_float4(0.f, 0.f, 0.f, 0.f);
    if (bias) bb = *(const float4*)&bias[n];
    #pragma unroll
    for (int i = 0; i < 4; i++) {
        int m = bm + ty * 4 + i;
        float4 r = make_float4(cr[i][0] + bb.x, cr[i][1] + bb.y,
                               cr[i][2] + bb.z, cr[i][3] + bb.w);
        if (act == 4) {
            r.x = softplusf(r.x); r.y = softplusf(r.y);
            r.z = softplusf(r.z); r.w = softplusf(r.w);
        }
        *(float4*)&C[(size_t)m * 32 + n] = r;
    }
}

// ---------------------------------------------------------------------------
// CSR build in ONE single-block launch (smem histogram + scan + fill)
// ---------------------------------------------------------------------------
__global__ void __launch_bounds__(1024)
csr_kernel(const int* __restrict__ src, const int* __restrict__ dst)
{
    __shared__ int sdeg[2048];
    __shared__ int sa[2048];
    __shared__ int sb[2048];
    int t = threadIdx.x;
    sdeg[t] = 0; sdeg[t + 1024] = 0;
    __syncthreads();
    for (int e = t; e < Ee; e += 1024) atomicAdd(&sdeg[dst[e]], 1);
    __syncthreads();
    sa[t] = sdeg[t]; sa[t + 1024] = sdeg[t + 1024];
    __syncthreads();
    int* cur = sa; int* nxt = sb;
    for (int off = 1; off < 2048; off <<= 1) {
        int i0 = t, i1 = t + 1024;
        nxt[i0] = cur[i0] + (i0 >= off ? cur[i0 - off] : 0);
        nxt[i1] = cur[i1] + (i1 >= off ? cur[i1 - off] : 0);
        __syncthreads();
        int* tmp = cur; cur = nxt; nxt = tmp;
    }
    d_rowptr[t + 1]    = cur[t];
    d_rowptr[t + 1025] = cur[t + 1024];
    if (t == 0) d_rowptr[0] = 0;
    float f0 = (float)(sdeg[t] + 1);
    float f1 = (float)(sdeg[t + 1024] + 1);
    d_degf[t] = f0;          d_dinv[t] = rsqrtf(f0);
    d_degf[t + 1024] = f1;   d_dinv[t + 1024] = rsqrtf(f1);
    __syncthreads();
    // reuse sdeg as per-node cursor
    sdeg[t] = 0; sdeg[t + 1024] = 0;
    __syncthreads();
    for (int e = t; e < Ee; e += 1024) {
        int d = dst[e];
        int pos = atomicAdd(&sdeg[d], 1);
        int base = (d == 0) ? 0 : cur[d - 1];
        d_csrsrc[base + pos] = src[e];
    }
}

// ---------------------------------------------------------------------------
// Graph gathers
// ---------------------------------------------------------------------------
__device__ __forceinline__ void gin512_body(const float4* __restrict__ x,
                                            float4* __restrict__ out, int n)
{
    int lane = threadIdx.x;   // 128 float4 lanes
    int beg = d_rowptr[n], end = d_rowptr[n + 1];
    float4 acc = x[(size_t)n * 128 + lane];
    for (int e = beg; e < end; e++) {
        float4 v = x[(size_t)d_csrsrc[e] * 128 + lane];
        acc.x += v.x; acc.y += v.y; acc.z += v.z; acc.w += v.w;
    }
    out[(size_t)n * 128 + lane] = acc;
}

__device__ __forceinline__ void gin256_body(const float4* __restrict__ x,
                                            float4* __restrict__ out, int pair)
{
    int lane = threadIdx.x & 63;
    int n = pair * 2 + (threadIdx.x >> 6);
    int beg = d_rowptr[n], end = d_rowptr[n + 1];
    float4 acc = x[(size_t)n * 64 + lane];
    for (int e = beg; e < end; e++) {
        float4 v = x[(size_t)d_csrsrc[e] * 64 + lane];
        acc.x += v.x; acc.y += v.y; acc.z += v.z; acc.w += v.w;
    }
    out[(size_t)n * 64 + lane] = acc;
}

__global__ void __launch_bounds__(128)
gin512_kernel(const float4* __restrict__ x, float4* __restrict__ out)
{
    gin512_body(x, out, blockIdx.x);
}

// l0: GPRE = gin(CAT) [512-wide, 2048 blocks] + HPRE = gin(h_l0) [1024 blocks]
__global__ void __launch_bounds__(128)
gin_l0_kernel(const float4* __restrict__ x512, float4* __restrict__ out512,
              const float4* __restrict__ x256, float4* __restrict__ out256)
{
    int bid = blockIdx.x;
    if (bid < 2048) gin512_body(x512, out512, bid);
    else            gin256_body(x256, out256, bid - 2048);
}

// l1: XPRE1 = gin(Hn l0) + HPRE = gin(h_l1), both 256-wide (1024 blocks each)
__global__ void __launch_bounds__(128)
gin_2x256_kernel(const float4* __restrict__ xA, float4* __restrict__ outA,
                 const float4* __restrict__ xB, float4* __restrict__ outB)
{
    int bid = blockIdx.x;
    if (bid < 1024) gin256_body(xA, outA, bid);
    else            gin256_body(xB, outB, bid - 1024);
}

__global__ void __launch_bounds__(128)
gin256_kernel(const float4* __restrict__ x, float4* __restrict__ out)
{
    gin256_body(x, out, blockIdx.x);
}

// Merged GCN (mean) + gin-softplus (std), 32-wide, blockIdx.y in 0..3
__global__ void __launch_bounds__(128)
gcnstd_kernel(const float4* __restrict__ XW, float4* __restrict__ MEAN,
              const float4* __restrict__ mean_b,
              const float4* __restrict__ STMP, float4* __restrict__ STD,
              const float4* __restrict__ std_b)
{
    int y = blockIdx.y;
    int lane = threadIdx.x & 7;
    int n = blockIdx.x * 16 + (threadIdx.x >> 3);
    int beg = d_rowptr[n], end = d_rowptr[n + 1];
    if (y < 2) {
        const float4* xw = XW + (size_t)y * (SZ_ZD / 4);
        float4* out = MEAN + (size_t)y * (SZ_ZD / 4);
        float4 b = mean_b[y * 8 + lane];
        float4 acc = make_float4(0.f, 0.f, 0.f, 0.f);
        for (int e = beg; e < end; e++) {
            int s = d_csrsrc[e];
            float w = d_dinv[s];
            float4 v = xw[(size_t)s * 8 + lane];
            acc.x += w * v.x; acc.y += w * v.y;
            acc.z += w * v.z; acc.w += w * v.w;
        }
        float dn = d_dinv[n], id = 1.f / d_degf[n];
        float4 xn = xw[(size_t)n * 8 + lane];
        out[(size_t)n * 8 + lane] = make_float4(
            dn * acc.x + id * xn.x + b.x, dn * acc.y + id * xn.y + b.y,
            dn * acc.z + id * xn.z + b.z, dn * acc.w + id * xn.w + b.w);
    } else {
        int zz = y - 2;
        const float4* tmp = STMP + (size_t)zz * (SZ_ZD / 4);
        float4* out = STD + (size_t)zz * (SZ_ZD / 4);
        float4 b = std_b[zz * 8 + lane];
        float4 acc = tmp[(size_t)n * 8 + lane];
        for (int e = beg; e < end; e++) {
            float4 v = tmp[(size_t)d_csrsrc[e] * 8 + lane];
            acc.x += v.x; acc.y += v.y; acc.z += v.z; acc.w += v.w;
        }
        out[(size_t)n * 8 + lane] = make_float4(
            softplusf(acc.x + b.x), softplusf(acc.y + b.y),
            softplusf(acc.z + b.z), softplusf(acc.w + b.w));
    }
}

// ---------------------------------------------------------------------------
// Init
// ---------------------------------------------------------------------------
__global__ void init_kernel() {
    size_t i = (size_t)blockIdx.x * blockDim.x + threadIdx.x;
    if (i < SZ_2HD)    g_f[O_CAT + i] = 0.f;   // CAT incl. h0 slot
    if (i < 2 * SZ_HD) g_f[O_H + i] = 0.f;     // h buffer 0, both layers
    if (i < 6) d_acc[i] = 0.0;
}

// ---------------------------------------------------------------------------
// Decoder (z_s @ z_d^T) fused with BCE partial sums (FFMA2; stride 66)
// ---------------------------------------------------------------------------
__global__ void __launch_bounds__(256)
dec_bce_kernel(const float* __restrict__ zs, const float* __restrict__ zd,
               const float* __restrict__ adj, float* __restrict__ dec)
{
    __shared__ float SsT[32][66];
    __shared__ float SdT[32][66];
    int tid = threadIdx.x;
    int bi = blockIdx.y * 64, bj = blockIdx.x * 64;
    for (int i = tid; i < 64 * 32; i += 256) {
        int r = i >> 5, c = i & 31;
        SsT[c][r] = zs[(size_t)(bi + r) * 32 + c];
        SdT[c][r] = zd[(size_t)(bj + r) * 32 + c];
    }
    __syncthreads();
    int tx = tid % 16, ty = tid / 16;
    u64 acc[2][4] = {};
    #pragma unroll
    for (int k = 0; k < 32; k++) {
        const u64* Ap = (const u64*)&SsT[k][ty * 4];
        u64 a0 = Ap[0], a1 = Ap[1];
        const float* bp = &SdT[k][tx * 4];
        u64 b0 = pack2(bp[0], bp[0]), b1 = pack2(bp[1], bp[1]);
        u64 b2 = pack2(bp[2], bp[2]), b3 = pack2(bp[3], bp[3]);
        ffma2(acc[0][0], a0, b0); ffma2(acc[0][1], a0, b1);
        ffma2(acc[0][2], a0, b2); ffma2(acc[0][3], a0, b3);
        ffma2(acc[1][0], a1, b0); ffma2(acc[1][1], a1, b1);
        ffma2(acc[1][2], a1, b2); ffma2(acc[1][3], a1, b3);
    }
    float cr[4][4];
    #pragma unroll
    for (int i2 = 0; i2 < 2; i2++)
        #pragma unroll
        for (int j = 0; j < 4; j++) {
            float2 p = unpack2(acc[i2][j]);
            cr[2 * i2][j] = p.x; cr[2 * i2 + 1][j] = p.y;
        }
    float sa = 0.f, s1 = 0.f, s2 = 0.f;
    #pragma unroll
    for (int i = 0; i < 4; i++) {
        int r = bi + ty * 4 + i;
        #pragma unroll
        for (int j = 0; j < 4; j++) {
            int c = bj + tx * 4 + j;
            float d = cr[i][j];
            dec[(size_t)r * Nn + c] = d;
            float a = adj[(size_t)r * Nn + c];
            float lg = log1pf(expf(-fabsf(d)));
            float lsp = fminf(d, 0.f) - lg;
            float lsn = fminf(-d, 0.f) - lg;
            sa += a; s1 += a * lsp; s2 += (1.f - a) * lsn;
        }
    }
    block_add(&d_acc[0], sa);
    block_add(&d_acc[1], s1);
    block_add(&d_acc[2], s2);
}

// ---------------------------------------------------------------------------
// KLD + per-step finalize
// ---------------------------------------------------------------------------
__device__ __forceinline__ float kterm(float m1, float s1, float m2, float s2) {
    float a = s1 + 1e-10f, b = s2 + 1e-10f;
    float dm = m1 - m2;
    return 2.f * (logf(b) - logf(a)) + (a * a + dm * dm) / (b * b) - 1.f;
}

__global__ void kld_kernel(const float* __restrict__ ms, const float* __restrict__ ss,
                           const float* __restrict__ pm, const float* __restrict__ ps,
                           const float* __restrict__ md, const float* __restrict__ sd,
                           const float* __restrict__ pmd, const float* __restrict__ psd)
{
    int i = blockIdx.x * blockDim.x + threadIdx.x;
    float v = 0.f;
    if (i < Nn * ZD)
        v = kterm(ms[i], ss[i], pm[i], ps[i]) + kterm(md[i], sd[i], pmd[i], psd[i]);
    block_add(&d_acc[3], v);
}

__global__ void finalize_kernel(float* __restrict__ out) {
    double ssum = d_acc[0], S1 = d_acc[1], S2 = d_acc[2], K = d_acc[3];
    double nn2 = (double)Nn * (double)Nn;
    double posw = (nn2 - ssum) / ssum;
    double nrm  = nn2 / ((nn2 - ssum) * 2.0);
    double nll  = nrm * ((-posw) * S1 - S2) / nn2;
    double kld  = 0.5 * K / nn2;
    d_acc[4] += kld;
    d_acc[5] += nll;
    out[0] = (float)d_acc[4];
    out[1] = (float)d_acc[5];
    d_acc[0] = 0.0; d_acc[1] = 0.0; d_acc[2] = 0.0; d_acc[3] = 0.0;
}

// ---------------------------------------------------------------------------
// Host orchestration
// ---------------------------------------------------------------------------
extern "C" void kernel_launch(void* const* d_in, const int* /*in_sizes*/, int /*n_in*/,
                              void* d_out, int /*out_size*/)
{
    const float* x       = (const float*)d_in[0];
    const int*   ei      = (const int*)  d_in[1];
    const float* adj     = (const float*)d_in[2];
    const float* eps_s   = (const float*)d_in[3];
    const float* eps_d   = (const float*)d_in[4];
    const float* phi_x_w = (const float*)d_in[5];
    const float* phi_z_w = (const float*)d_in[6];
    const float* gxw0    = (const float*)d_in[7];   // [3,512,256]
    const float* gxw1    = (const float*)d_in[8];   // [3,256,256]
    const float* ghw     = (const float*)d_in[9];   // [2,3,256,256]
    const float* enc_w   = (const float*)d_in[10];  // [2,512,256]
    const float* enc_b   = (const float*)d_in[11];
    const float* mean_w  = (const float*)d_in[12];  // [2,256,32]
    const float* mean_b  = (const float*)d_in[13];
    const float* std_w   = (const float*)d_in[14];
    const float* std_b   = (const float*)d_in[15];
    const float* pri_w   = (const float*)d_in[16];  // [2,256,256]
    const float* pri_b   = (const float*)d_in[17];
    const float* pri_mw  = (const float*)d_in[18];
    const float* pri_mb  = (const float*)d_in[19];
    const float* pri_sw  = (const float*)d_in[20];
    const float* pri_sb  = (const float*)d_in[21];
    float* out = (float*)d_out;
    float* dec_out = out + 2;  // [T, N, N]

    float* F = nullptr;
    cudaGetSymbolAddress((void**)&F, g_f);

    float* CAT    = F + O_CAT;
    float* CATP   = F + O_CATP;
    float* ENC_S  = F + O_ENC_S;
    float* XW_S   = F + O_XW_S;
    float* MEAN_S = F + O_MEAN_S;
    float* MEAN_D = F + O_MEAN_D;
    float* STMP_S = F + O_STMP_S;
    float* STD_S  = F + O_STD_S;
    float* STD_D  = F + O_STD_D;
    float* PRI_S  = F + O_PRI_S;
    float* PM_S   = F + O_PM_S;
    float* PS_S   = F + O_PS_S;
    float* PM_D   = F + O_PM_D;
    float* PS_D   = F + O_PS_D;
    float* Z_S    = F + O_Z_S;
    float* Z_D    = F + O_Z_D;
    float* GPRE   = F + O_GPRE;
    float* HPRE   = F + O_HPRE;
    float* XPRE1  = F + O_XPRE1;
    float* TZ     = F + O_TZ;
    float* TH     = F + O_TH;
    float* RH     = F + O_RH;
    float* RHP    = F + O_RHP;

    init_kernel<<<(SZ_2HD + 255) / 256, 256>>>();

    for (int t = 0; t < Tt; t++) {
        const float* x_t   = x + (size_t)t * Nn * XD;
        const int*   src_t = ei + (size_t)t * 2 * Ee;
        const int*   dst_t = src_t + Ee;
        const float* adj_t = adj + (size_t)t * Nn * Nn;
        const float* es_t  = eps_s + (size_t)t * SZ_ZD;
        const float* ed_t  = eps_d + (size_t)t * SZ_ZD;
        float* Hc = F + O_H + (size_t)(t & 1) * 2 * SZ_HD;
        float* Hn = F + O_H + (size_t)((t + 1) & 1) * 2 * SZ_HD;
        float* hlast = Hc + SZ_HD;
        float* dec_t = dec_out + (size_t)t * Nn * Nn;

        // --- CSR (one launch) ---
        csr_kernel<<<1, 1024>>>(src_t, dst_t);

        // --- phi_x into CAT[:,0:256]; right half holds h_last from prev step ---
        sgemm64<1><<<dim3(4, 32, 1), 128>>>(x_t, phi_x_w, nullptr, CAT,
                                            XD, XD, 256, 512, 0, 0, 0, 0);

        // --- cat_pre = gin(cat) ---
        gin512_kernel<<<2048, 128>>>((const float4*)CAT, (float4*)CATP);

        // --- encoders + priors, grouped (z=4) ---
        encpri_kernel<<<dim3(4, 32, 4), 128>>>(CATP, hlast, enc_w, enc_b,
                                               pri_w, pri_b, ENC_S, PRI_S);

        // --- all eight ZD=32 GEMMs, grouped ---
        g32_kernel<<<dim3(1, 32, 8), 128>>>(ENC_S, PRI_S, mean_w, std_w,
                                            pri_mw, pri_mb, pri_sw, pri_sb,
                                            XW_S, STMP_S, PM_S);

        // --- GCN(mean) + gin-softplus(std), grouped (y=4) ---
        gcnstd_kernel<<<dim3(Nn / 16, 4), 128>>>(
            (const float4*)XW_S, (float4*)MEAN_S, (const float4*)mean_b,
            (const float4*)STMP_S, (float4*)STD_S, (const float4*)std_b);

        // --- phi_z with inline reparameterization -> CAT[:,256:512]; Z persisted ---
        phi_z_kernel<<<dim3(4, 32), 128>>>(
            (const float4*)MEAN_S, (const float4*)STD_S, (const float4*)es_t,
            (const float4*)MEAN_D, (const float4*)STD_D, (const float4*)ed_t,
            phi_z_w, CAT + 256, (float4*)Z_S, (float4*)Z_D);

        // --- decoder + fused BCE sums; KLD; finalize ---
        dec_bce_kernel<<<dim3(Nn / 64, Nn / 64), 256>>>(Z_S, Z_D, adj_t, dec_t);
        kld_kernel<<<(Nn * ZD + 255) / 256, 256>>>(MEAN_S, STD_S, PM_S, PS_S,
                                                   MEAN_D, STD_D, PM_D, PS_D);
        finalize_kernel<<<1, 1>>>(out);

        // --- graph-GRU, 2 layers ---
        for (int l = 0; l < 2; l++) {
            const float* xi  = (l == 0) ? CAT : Hn;
            float* xpre      = (l == 0) ? GPRE : XPRE1;
            int Kx           = (l == 0) ? 512 : 256;
            const float* xw  = (l == 0) ? gxw0 : gxw1;
            const float* hw  = ghw + (size_t)l * 3 * 256 * 256;
            float* h_l       = Hc + (size_t)l * SZ_HD;
            float* h_out     = Hn + (size_t)l * SZ_HD;
            float* out2      = (l == 1) ? (CAT + 256) : nullptr;

            if (l == 0)
                gin_l0_kernel<<<3072, 128>>>((const float4*)xi, (float4*)xpre,
                                             (const float4*)h_l, (float4*)HPRE);
            else
                gin_2x256_kernel<<<2048, 128>>>((const float4*)xi, (float4*)xpre,
                                                (const float4*)h_l, (float4*)HPRE);

            // x-side of all 3 gates, batched z=3 -> TZ|TR|TH
            sgemm64<0><<<dim3(4, 32, 3), 128>>>(xpre, xw, nullptr, TZ,
                                                Kx, Kx, 256, 256,
                                                0, (size_t)Kx * 256, 0, SZ_HD);
            // h-side z,r gates fused
            sgemm64_zr<<<dim3(4, 32, 2), 128>>>(HPRE, hw, TZ, h_l, TZ, RH, 256, 256);
            // candidate
            gin256_kernel<<<1024, 128>>>((const float4*)RH, (float4*)RHP);
            sgemm64_cand<<<dim3(4, 32), 128>>>(RHP, hw + 2 * 256 * 256,
                                               TH, TZ, h_l, h_out, out2, 256, 256);
        }
    }
}

// round 9
// speedup vs baseline: 2.3047x; 1.0405x over previous
#include <cuda_runtime.h>
#include <cstdint>
#include <cstddef>

// ---------------------------------------------------------------------------
// Problem constants
// ---------------------------------------------------------------------------
#define Nn 2048
#define Ee 32768
#define Tt 12
#define XD 128
#define HD 256
#define ZD 32

constexpr size_t SZ_HD  = (size_t)Nn * HD;      // 524288
constexpr size_t SZ_2HD = (size_t)Nn * 2 * HD;  // 1048576
constexpr size_t SZ_ZD  = (size_t)Nn * ZD;      // 65536

// ---------------------------------------------------------------------------
// Scratch layout (adjacency is load-bearing for batched/grouped GEMMs)
// ---------------------------------------------------------------------------
constexpr size_t O_CAT   = 0;                    // [N,512]  (phi_x | h1/phi_z)
constexpr size_t O_CATP  = O_CAT   + SZ_2HD;     // gin(cat)
constexpr size_t O_ENC_S = O_CATP  + SZ_2HD;
constexpr size_t O_ENC_D = O_ENC_S + SZ_HD;
constexpr size_t O_XW_S  = O_ENC_D + SZ_HD;
constexpr size_t O_XW_D  = O_XW_S  + SZ_ZD;
constexpr size_t O_MEAN_S= O_XW_D  + SZ_ZD;
constexpr size_t O_MEAN_D= O_MEAN_S+ SZ_ZD;
constexpr size_t O_STMP_S= O_MEAN_D+ SZ_ZD;
constexpr size_t O_STMP_D= O_STMP_S+ SZ_ZD;
constexpr size_t O_STD_S = O_STMP_D+ SZ_ZD;
constexpr size_t O_STD_D = O_STD_S + SZ_ZD;
constexpr size_t O_PRI_S = O_STD_D + SZ_ZD;
constexpr size_t O_PRI_D = O_PRI_S + SZ_HD;
constexpr size_t O_PM_S  = O_PRI_D + SZ_HD;      // PM_S|PS_S|PM_D|PS_D
constexpr size_t O_PS_S  = O_PM_S  + SZ_ZD;
constexpr size_t O_PM_D  = O_PS_S  + SZ_ZD;
constexpr size_t O_PS_D  = O_PM_D  + SZ_ZD;
constexpr size_t O_Z_S   = O_PS_D  + SZ_ZD;
constexpr size_t O_Z_D   = O_Z_S   + SZ_ZD;
constexpr size_t O_GPRE  = O_Z_D   + SZ_ZD;      // gin(g_in) [N,512]
constexpr size_t O_HPRE  = O_GPRE  + SZ_2HD;     // gin(h[i]) [N,256]
constexpr size_t O_XPRE1 = O_HPRE  + SZ_HD;      // gin(new_h0) [N,256]
constexpr size_t O_TZ    = O_XPRE1 + SZ_HD;
constexpr size_t O_TR    = O_TZ    + SZ_HD;      // (spare)
constexpr size_t O_TH    = O_TR    + SZ_HD;
constexpr size_t O_RH    = O_TH    + SZ_HD;
constexpr size_t O_RHP   = O_RH    + SZ_HD;
constexpr size_t O_H     = O_RHP   + SZ_HD;      // 2 dbl-buffers x NL layers
constexpr size_t TOTAL_F = O_H + 4 * SZ_HD;

__device__ __align__(256) float g_f[TOTAL_F];
__device__ int    d_rowptr[Nn + 1];
__device__ int    d_csrsrc[Ee];
__device__ float  d_degf[Nn];
__device__ float  d_dinv[Nn];
__device__ double d_acc[6];

// ---------------------------------------------------------------------------
// f32x2 packed-FMA helpers (Blackwell FFMA2 via PTX)
// ---------------------------------------------------------------------------
typedef unsigned long long u64;

__device__ __forceinline__ u64 pack2(float x, float y) {
    u64 r; asm("mov.b64 %0, {%1, %2};" : "=l"(r) : "f"(x), "f"(y)); return r;
}
__device__ __forceinline__ void ffma2(u64& c, u64 a, u64 b) {
    asm("fma.rn.f32x2 %0, %1, %2, %0;" : "+l"(c) : "l"(a), "l"(b));
}
__device__ __forceinline__ float2 unpack2(u64 v) {
    float2 r; asm("mov.b64 {%0, %1}, %2;" : "=f"(r.x), "=f"(r.y) : "l"(v)); return r;
}

// ---------------------------------------------------------------------------
// Activations / reductions
// ---------------------------------------------------------------------------
template<int ACT>
__device__ __forceinline__ float activate(float v) {
    if (ACT == 1) return fmaxf(v, 0.f);
    if (ACT == 2) return 1.f / (1.f + expf(-v));
    if (ACT == 3) return tanhf(v);
    if (ACT == 4) return fmaxf(v, 0.f) + log1pf(expf(-fabsf(v)));  // softplus
    return v;
}

__device__ __forceinline__ float softplusf(float v) {
    return fmaxf(v, 0.f) + log1pf(expf(-fabsf(v)));
}

__device__ __forceinline__ void block_add(double* target, float v) {
    #pragma unroll
    for (int o = 16; o; o >>= 1) v += __shfl_down_sync(0xffffffffu, v, o);
    __shared__ float wsum[32];
    int lane = threadIdx.x & 31, wid = threadIdx.x >> 5;
    if (lane == 0) wsum[wid] = v;
    __syncthreads();
    if (threadIdx.x == 0) {
        float s = 0.f;
        int nw = (blockDim.x + 31) >> 5;
        for (int i = 0; i < nw; i++) s += wsum[i];
        atomicAdd(target, (double)s);
    }
    __syncthreads();
}

// ---------------------------------------------------------------------------
// 64x64x16 FFMA2 mainloop pieces (128 threads, 8x4 micro-tile)
// ---------------------------------------------------------------------------
__device__ __forceinline__ void stageA(const float* __restrict__ A, int lda,
                                       int bm, int ka, float* Asf, int tid)
{
    #pragma unroll
    for (int it = 0; it < 2; it++) {
        int idx = tid + it * 128;
        int m = idx >> 2, c4 = idx & 3;
        float4 v = *(const float4*)&A[(size_t)(bm + m) * lda + ka + c4 * 4];
        Asf[(c4 * 4 + 0) * 64 + m] = v.x;
        Asf[(c4 * 4 + 1) * 64 + m] = v.y;
        Asf[(c4 * 4 + 2) * 64 + m] = v.z;
        Asf[(c4 * 4 + 3) * 64 + m] = v.w;
    }
}

__device__ __forceinline__ void stageB(const float* __restrict__ Bk, int ldb,
                                       int bn, float4 (*Bs)[16], int tid)
{
    #pragma unroll
    for (int it = 0; it < 2; it++) {
        int idx = tid + it * 128;
        int k = idx >> 4, n4 = idx & 15;
        Bs[k][n4] = *(const float4*)&Bk[(size_t)k * ldb + bn + n4 * 4];
    }
}

__device__ __forceinline__ void fma_tile(const float* Asf, float4 (*Bs)[16],
                                         int tx, int ty, u64 acc[4][4])
{
    #pragma unroll
    for (int k = 0; k < 16; k++) {
        const u64* Ap = (const u64*)&Asf[k * 64 + ty * 8];
        u64 a0 = Ap[0], a1 = Ap[1], a2 = Ap[2], a3 = Ap[3];
        float4 b = Bs[k][tx];
        u64 b0 = pack2(b.x, b.x), b1 = pack2(b.y, b.y);
        u64 b2 = pack2(b.z, b.z), b3 = pack2(b.w, b.w);
        ffma2(acc[0][0], a0, b0); ffma2(acc[0][1], a0, b1);
        ffma2(acc[0][2], a0, b2); ffma2(acc[0][3], a0, b3);
        ffma2(acc[1][0], a1, b0); ffma2(acc[1][1], a1, b1);
        ffma2(acc[1][2], a1, b2); ffma2(acc[1][3], a1, b3);
        ffma2(acc[2][0], a2, b0); ffma2(acc[2][1], a2, b1);
        ffma2(acc[2][2], a2, b2); ffma2(acc[2][3], a2, b3);
        ffma2(acc[3][0], a3, b0); ffma2(acc[3][1], a3, b1);
        ffma2(acc[3][2], a3, b2); ffma2(acc[3][3], a3, b3);
    }
}

__device__ __forceinline__ void mainloop64(
    const float* __restrict__ A, const float* __restrict__ B,
    int K, int lda, int ldb, int bm, int bn,
    float4 (*As)[16], float4 (*Bs)[16], u64 acc[4][4])
{
    const int tid = threadIdx.x;
    const int tx = tid & 15, ty = tid >> 4;
    float* Asf = (float*)As;
    for (int k0 = 0; k0 < K; k0 += 16) {
        stageA(A, lda, bm, k0, Asf, tid);
        stageB(B + (size_t)k0 * ldb, ldb, bn, Bs, tid);
        __syncthreads();
        fma_tile(Asf, Bs, tx, ty, acc);
        __syncthreads();
    }
}

__device__ __forceinline__ void unpack_acc64(u64 acc[4][4], float cr[8][4]) {
    #pragma unroll
    for (int i2 = 0; i2 < 4; i2++)
        #pragma unroll
        for (int j = 0; j < 4; j++) {
            float2 p = unpack2(acc[i2][j]);
            cr[2 * i2][j] = p.x;
            cr[2 * i2 + 1][j] = p.y;
        }
}

// Generic GEMM: C = act( A@B (+bias) ), batched over gridDim.z
template<int ACT>
__global__ void __launch_bounds__(128)
sgemm64(const float* __restrict__ A, const float* __restrict__ B,
        const float* __restrict__ bias, float* __restrict__ C,
        int K, int lda, int ldb, int ldc,
        size_t sA, size_t sB, size_t sBias, size_t sC)
{
    __shared__ float4 As[16][16];
    __shared__ float4 Bs[16][16];
    const int z = blockIdx.z;
    A += (size_t)z * sA; B += (size_t)z * sB; C += (size_t)z * sC;
    const float* biasz = bias ? bias + (size_t)z * sBias : nullptr;
    const int bm = blockIdx.y * 64, bn = blockIdx.x * 64;
    const int tx = threadIdx.x & 15, ty = threadIdx.x >> 4;

    u64 acc[4][4] = {};
    mainloop64(A, B, K, lda, ldb, bm, bn, As, Bs, acc);
    float cr[8][4];
    unpack_acc64(acc, cr);

    const int n = bn + tx * 4;
    float4 bb = make_float4(0.f, 0.f, 0.f, 0.f);
    if (biasz) bb = *(const float4*)&biasz[n];
    #pragma unroll
    for (int i = 0; i < 8; i++) {
        int m = bm + ty * 8 + i;
        float4 r;
        r.x = activate<ACT>(cr[i][0] + bb.x);
        r.y = activate<ACT>(cr[i][1] + bb.y);
        r.z = activate<ACT>(cr[i][2] + bb.z);
        r.w = activate<ACT>(cr[i][3] + bb.w);
        *(float4*)&C[(size_t)m * ldc + n] = r;
    }
}

// Grouped encoders + priors: z0/z1 = enc_s/enc_d (K=512, A=CATP),
// z2/z3 = pri_s/pri_d (K=256, A=hlast). All relu+bias, ldc=256.
__global__ void __launch_bounds__(128)
encpri_kernel(const float* __restrict__ CATP, const float* __restrict__ hlast,
              const float* __restrict__ enc_w, const float* __restrict__ enc_b,
              const float* __restrict__ pri_w, const float* __restrict__ pri_b,
              float* __restrict__ ENC_S, float* __restrict__ PRI_S)
{
    __shared__ float4 As[16][16];
    __shared__ float4 Bs[16][16];
    const int z = blockIdx.z;
    const float* A; const float* B; const float* bias; float* C;
    int K, lda;
    if (z < 2) {
        A = CATP; K = 512; lda = 512;
        B = enc_w + (size_t)z * 512 * 256;
        bias = enc_b + (size_t)z * 256;
        C = ENC_S + (size_t)z * SZ_HD;
    } else {
        A = hlast; K = 256; lda = 256;
        B = pri_w + (size_t)(z - 2) * 256 * 256;
        bias = pri_b + (size_t)(z - 2) * 256;
        C = PRI_S + (size_t)(z - 2) * SZ_HD;
    }
    const int bm = blockIdx.y * 64, bn = blockIdx.x * 64;
    const int tx = threadIdx.x & 15, ty = threadIdx.x >> 4;

    u64 acc[4][4] = {};
    mainloop64(A, B, K, lda, 256, bm, bn, As, Bs, acc);
    float cr[8][4];
    unpack_acc64(acc, cr);

    const int n = bn + tx * 4;
    float4 bb = *(const float4*)&bias[n];
    #pragma unroll
    for (int i = 0; i < 8; i++) {
        int m = bm + ty * 8 + i;
        float4 r;
        r.x = fmaxf(cr[i][0] + bb.x, 0.f);
        r.y = fmaxf(cr[i][1] + bb.y, 0.f);
        r.z = fmaxf(cr[i][2] + bb.z, 0.f);
        r.w = fmaxf(cr[i][3] + bb.w, 0.f);
        *(float4*)&C[(size_t)m * 256 + n] = r;
    }
}

// ---------------------------------------------------------------------------
// GRU gates, all in one launch via virtual K-concat:
//   z=0: TZ = sigmoid( xpre@xw[0] + hpre@hw[0] )        (K = Kx+256)
//   z=1: RH = sigmoid( xpre@xw[1] + hpre@hw[1] ) * h    (K = Kx+256)
//   z=2: TH = xpre@xw[2]                                (K = Kx)
// ---------------------------------------------------------------------------
__global__ void __launch_bounds__(128)
gru_gates_kernel(const float* __restrict__ xpre, const float* __restrict__ hpre,
                 const float* __restrict__ xw, const float* __restrict__ hw,
                 const float* __restrict__ h, float* __restrict__ TZ,
                 float* __restrict__ RH, float* __restrict__ TH, int Kx)
{
    __shared__ float4 As[16][16];
    __shared__ float4 Bs[16][16];
    const int z = blockIdx.z;
    const float* Bx = xw + (size_t)z * Kx * 256;
    const float* Bh = hw + (size_t)z * 256 * 256;
    const int Ktot = (z == 2) ? Kx : Kx + 256;
    const int tid = threadIdx.x;
    const int bm = blockIdx.y * 64, bn = blockIdx.x * 64;
    const int tx = tid & 15, ty = tid >> 4;
    float* Asf = (float*)As;

    u64 acc[4][4] = {};
    for (int k0 = 0; k0 < Ktot; k0 += 16) {
        if (k0 < Kx) {
            stageA(xpre, Kx, bm, k0, Asf, tid);
            stageB(Bx + (size_t)k0 * 256, 256, bn, Bs, tid);
        } else {
            stageA(hpre, 256, bm, k0 - Kx, Asf, tid);
            stageB(Bh + (size_t)(k0 - Kx) * 256, 256, bn, Bs, tid);
        }
        __syncthreads();
        fma_tile(Asf, Bs, tx, ty, acc);
        __syncthreads();
    }
    float cr[8][4];
    unpack_acc64(acc, cr);

    const int n = bn + tx * 4;
    #pragma unroll
    for (int i = 0; i < 8; i++) {
        int m = bm + ty * 8 + i;
        float4 r = make_float4(cr[i][0], cr[i][1], cr[i][2], cr[i][3]);
        if (z == 2) {
            *(float4*)&TH[(size_t)m * 256 + n] = r;
        } else {
            r.x = activate<2>(r.x); r.y = activate<2>(r.y);
            r.z = activate<2>(r.z); r.w = activate<2>(r.w);
            if (z == 0) {
                *(float4*)&TZ[(size_t)m * 256 + n] = r;
            } else {
                float4 hh = *(const float4*)&h[(size_t)m * 256 + n];
                r.x *= hh.x; r.y *= hh.y; r.z *= hh.z; r.w *= hh.w;
                *(float4*)&RH[(size_t)m * 256 + n] = r;
            }
        }
    }
}

// GRU candidate fused: ht = tanh(TH + A@B); h_out = TZ*h + (1-TZ)*ht;
// optionally dual-write h_out into out2 (ld 512).
__global__ void __launch_bounds__(128)
sgemm64_cand(const float* __restrict__ A, const float* __restrict__ B,
             const float* __restrict__ TH, const float* __restrict__ TZ,
             const float* __restrict__ h, float* __restrict__ h_out,
             float* __restrict__ out2, int K, int lda)
{
    __shared__ float4 As[16][16];
    __shared__ float4 Bs[16][16];
    const int bm = blockIdx.y * 64, bn = blockIdx.x * 64;
    const int tx = threadIdx.x & 15, ty = threadIdx.x >> 4;

    u64 acc[4][4] = {};
    mainloop64(A, B, K, lda, 256, bm, bn, As, Bs, acc);
    float cr[8][4];
    unpack_acc64(acc, cr);

    const int n = bn + tx * 4;
    #pragma unroll
    for (int i = 0; i < 8; i++) {
        int m = bm + ty * 8 + i;
        float4 th = *(const float4*)&TH[(size_t)m * 256 + n];
        float4 zg = *(const float4*)&TZ[(size_t)m * 256 + n];
        float4 hh = *(const float4*)&h[(size_t)m * 256 + n];
        float4 r;
        r.x = zg.x * hh.x + (1.f - zg.x) * tanhf(cr[i][0] + th.x);
        r.y = zg.y * hh.y + (1.f - zg.y) * tanhf(cr[i][1] + th.y);
        r.z = zg.z * hh.z + (1.f - zg.z) * tanhf(cr[i][2] + th.z);
        r.w = zg.w * hh.w + (1.f - zg.w) * tanhf(cr[i][3] + th.w);
        *(float4*)&h_out[(size_t)m * 256 + n] = r;
        if (out2) *(float4*)&out2[(size_t)m * 512 + n] = r;
    }
}

// phi_z GEMM with inline reparameterization (see R7 notes)
__global__ void __launch_bounds__(128)
phi_z_kernel(const float4* __restrict__ ms, const float4* __restrict__ ss,
             const float4* __restrict__ es, const float4* __restrict__ md,
             const float4* __restrict__ sd, const float4* __restrict__ ed,
             const float* __restrict__ W, float* __restrict__ C,
             float4* __restrict__ zs4, float4* __restrict__ zd4)
{
    __shared__ float4 As[16][16];
    __shared__ float4 Bs[16][16];
    const int tid = threadIdx.x;
    const int bm = blockIdx.y * 64, bn = blockIdx.x * 64;
    const int tx = tid & 15, ty = tid >> 4;
    float* Asf = (float*)As;

    u64 acc[4][4] = {};
    for (int k0 = 0; k0 < 64; k0 += 16) {
        #pragma unroll
        for (int it = 0; it < 2; it++) {
            int idx = tid + it * 128;
            int m = idx >> 2, c4 = idx & 3;
            int n = bm + m;
            int kk = k0 + c4 * 4;
            float4 v;
            if (kk < 32) {
                int j4 = kk >> 2;
                float4 a = ms[(size_t)n * 8 + j4];
                float4 s = ss[(size_t)n * 8 + j4];
                float4 e = es[(size_t)n * 8 + j4];
                v = make_float4(a.x + s.x * e.x, a.y + s.y * e.y,
                                a.z + s.z * e.z, a.w + s.w * e.w);
                if (blockIdx.x == 0) zs4[(size_t)n * 8 + j4] = v;
            } else {
                int j4 = (kk - 32) >> 2;
                float4 a = md[(size_t)n * 8 + j4];
                float4 s = sd[(size_t)n * 8 + j4];
                float4 e = ed[(size_t)n * 8 + j4];
                v = make_float4(a.x + s.x * e.x, a.y + s.y * e.y,
                                a.z + s.z * e.z, a.w + s.w * e.w);
                if (blockIdx.x == 0) zd4[(size_t)n * 8 + j4] = v;
            }
            Asf[(c4 * 4 + 0) * 64 + m] = v.x;
            Asf[(c4 * 4 + 1) * 64 + m] = v.y;
            Asf[(c4 * 4 + 2) * 64 + m] = v.z;
            Asf[(c4 * 4 + 3) * 64 + m] = v.w;
        }
        stageB(W + (size_t)k0 * 256, 256, bn, Bs, tid);
        __syncthreads();
        fma_tile(Asf, Bs, tx, ty, acc);
        __syncthreads();
    }
    float cr[8][4];
    unpack_acc64(acc, cr);
    const int n = bn + tx * 4;
    #pragma unroll
    for (int i = 0; i < 8; i++) {
        int m = bm + ty * 8 + i;
        float4 r;
        r.x = fmaxf(cr[i][0], 0.f);
        r.y = fmaxf(cr[i][1], 0.f);
        r.z = fmaxf(cr[i][2], 0.f);
        r.w = fmaxf(cr[i][3], 0.f);
        *(float4*)&C[(size_t)m * 512 + n] = r;
    }
}

// Grouped 64x32x16 GEMMs: 8 jobs via blockIdx.z (see R7 notes)
__global__ void __launch_bounds__(128)
g32_kernel(const float* __restrict__ ENC_S, const float* __restrict__ PRI_S,
           const float* __restrict__ mean_w, const float* __restrict__ std_w,
           const float* __restrict__ pri_mw, const float* __restrict__ pri_mb,
           const float* __restrict__ pri_sw, const float* __restrict__ pri_sb,
           float* __restrict__ XW_S, float* __restrict__ STMP_S,
           float* __restrict__ PM_S)
{
    __shared__ float4 As[16][16];
    __shared__ float4 Bs[16][8];
    const int z = blockIdx.z;
    const float* A; const float* B; const float* bias = nullptr; float* C;
    int act = 0;
    switch (z) {
        case 0: A = ENC_S;          B = mean_w;        C = XW_S;                break;
        case 1: A = ENC_S + SZ_HD;  B = mean_w + 8192; C = XW_S + SZ_ZD;        break;
        case 2: A = ENC_S;          B = std_w;         C = STMP_S;              break;
        case 3: A = ENC_S + SZ_HD;  B = std_w + 8192;  C = STMP_S + SZ_ZD;      break;
        case 4: A = PRI_S;          B = pri_mw;        C = PM_S;
                bias = pri_mb;                                                  break;
        case 5: A = PRI_S;          B = pri_sw;        C = PM_S + SZ_ZD;
                bias = pri_sb; act = 4;                                         break;
        case 6: A = PRI_S + SZ_HD;  B = pri_mw + 8192; C = PM_S + 2 * SZ_ZD;
                bias = pri_mb + 32;                                             break;
        default:A = PRI_S + SZ_HD;  B = pri_sw + 8192; C = PM_S + 3 * SZ_ZD;
                bias = pri_sb + 32; act = 4;                                    break;
    }

    const int tid = threadIdx.x;
    const int bm = blockIdx.y * 64;
    const int tx = tid & 7;
    const int ty = tid >> 3;

    u64 acc[2][4] = {};
    float* Asf = (float*)As;

    for (int k0 = 0; k0 < 256; k0 += 16) {
        stageA(A, 256, bm, k0, Asf, tid);
        {
            int k = tid >> 3, n4 = tid & 7;
            Bs[k][n4] = *(const float4*)&B[(size_t)(k0 + k) * 32 + n4 * 4];
        }
        __syncthreads();
        #pragma unroll
        for (int k = 0; k < 16; k++) {
            const u64* Ap = (const u64*)&Asf[k * 64 + ty * 4];
            u64 a0 = Ap[0], a1 = Ap[1];
            float4 b = Bs[k][tx];
            u64 b0 = pack2(b.x, b.x), b1 = pack2(b.y, b.y);
            u64 b2 = pack2(b.z, b.z), b3 = pack2(b.w, b.w);
            ffma2(acc[0][0], a0, b0); ffma2(acc[0][1], a0, b1);
            ffma2(acc[0][2], a0, b2); ffma2(acc[0][3], a0, b3);
            ffma2(acc[1][0], a1, b0); ffma2(acc[1][1], a1, b1);
            ffma2(acc[1][2], a1, b2); ffma2(acc[1][3], a1, b3);
        }
        __syncthreads();
    }

    float cr[4][4];
    #pragma unroll
    for (int i2 = 0; i2 < 2; i2++)
        #pragma unroll
        for (int j = 0; j < 4; j++) {
            float2 p = unpack2(acc[i2][j]);
            cr[2 * i2][j] = p.x; cr[2 * i2 + 1][j] = p.y;
        }

    const int n = tx * 4;
    float4 bb = make_float4(0.f, 0.f, 0.f, 0.f);
    if (bias) bb = *(const float4*)&bias[n];
    #pragma unroll
    for (int i = 0; i < 4; i++) {
        int m = bm + ty * 4 + i;
        float4 r = make_float4(cr[i][0] + bb.x, cr[i][1] + bb.y,
                               cr[i][2] + bb.z, cr[i][3] + bb.w);
        if (act == 4) {
            r.x = softplusf(r.x); r.y = softplusf(r.y);
            r.z = softplusf(r.z); r.w = softplusf(r.w);
        }
        *(float4*)&C[(size_t)m * 32 + n] = r;
    }
}

// ---------------------------------------------------------------------------
// CSR build in ONE single-block launch
// ---------------------------------------------------------------------------
__global__ void __launch_bounds__(1024)
csr_kernel(const int* __restrict__ src, const int* __restrict__ dst)
{
    __shared__ int sdeg[2048];
    __shared__ int sa[2048];
    __shared__ int sb[2048];
    int t = threadIdx.x;
    sdeg[t] = 0; sdeg[t + 1024] = 0;
    __syncthreads();
    for (int e = t; e < Ee; e += 1024) atomicAdd(&sdeg[dst[e]], 1);
    __syncthreads();
    sa[t] = sdeg[t]; sa[t + 1024] = sdeg[t + 1024];
    __syncthreads();
    int* cur = sa; int* nxt = sb;
    for (int off = 1; off < 2048; off <<= 1) {
        int i0 = t, i1 = t + 1024;
        nxt[i0] = cur[i0] + (i0 >= off ? cur[i0 - off] : 0);
        nxt[i1] = cur[i1] + (i1 >= off ? cur[i1 - off] : 0);
        __syncthreads();
        int* tmp = cur; cur = nxt; nxt = tmp;
    }
    d_rowptr[t + 1]    = cur[t];
    d_rowptr[t + 1025] = cur[t + 1024];
    if (t == 0) d_rowptr[0] = 0;
    float f0 = (float)(sdeg[t] + 1);
    float f1 = (float)(sdeg[t + 1024] + 1);
    d_degf[t] = f0;          d_dinv[t] = rsqrtf(f0);
    d_degf[t + 1024] = f1;   d_dinv[t + 1024] = rsqrtf(f1);
    __syncthreads();
    sdeg[t] = 0; sdeg[t + 1024] = 0;
    __syncthreads();
    for (int e = t; e < Ee; e += 1024) {
        int d = dst[e];
        int pos = atomicAdd(&sdeg[d], 1);
        int base = (d == 0) ? 0 : cur[d - 1];
        d_csrsrc[base + pos] = src[e];
    }
}

// ---------------------------------------------------------------------------
// Graph gathers (edge loops unrolled x4 for MLP)
// ---------------------------------------------------------------------------
#define F4ADD(a, v) { (a).x += (v).x; (a).y += (v).y; (a).z += (v).z; (a).w += (v).w; }

__device__ __forceinline__ void gin512_body(const float4* __restrict__ x,
                                            float4* __restrict__ out, int n)
{
    int lane = threadIdx.x;   // 128 float4 lanes
    int beg = d_rowptr[n], end = d_rowptr[n + 1];
    float4 acc = x[(size_t)n * 128 + lane];
    int e = beg;
    for (; e + 4 <= end; e += 4) {
        int s0 = d_csrsrc[e],     s1 = d_csrsrc[e + 1];
        int s2 = d_csrsrc[e + 2], s3 = d_csrsrc[e + 3];
        float4 v0 = x[(size_t)s0 * 128 + lane];
        float4 v1 = x[(size_t)s1 * 128 + lane];
        float4 v2 = x[(size_t)s2 * 128 + lane];
        float4 v3 = x[(size_t)s3 * 128 + lane];
        F4ADD(acc, v0); F4ADD(acc, v1); F4ADD(acc, v2); F4ADD(acc, v3);
    }
    for (; e < end; e++) {
        float4 v = x[(size_t)d_csrsrc[e] * 128 + lane];
        F4ADD(acc, v);
    }
    out[(size_t)n * 128 + lane] = acc;
}

__device__ __forceinline__ void gin256_body(const float4* __restrict__ x,
                                            float4* __restrict__ out, int pair)
{
    int lane = threadIdx.x & 63;
    int n = pair * 2 + (threadIdx.x >> 6);
    int beg = d_rowptr[n], end = d_rowptr[n + 1];
    float4 acc = x[(size_t)n * 64 + lane];
    int e = beg;
    for (; e + 4 <= end; e += 4) {
        int s0 = d_csrsrc[e],     s1 = d_csrsrc[e + 1];
        int s2 = d_csrsrc[e + 2], s3 = d_csrsrc[e + 3];
        float4 v0 = x[(size_t)s0 * 64 + lane];
        float4 v1 = x[(size_t)s1 * 64 + lane];
        float4 v2 = x[(size_t)s2 * 64 + lane];
        float4 v3 = x[(size_t)s3 * 64 + lane];
        F4ADD(acc, v0); F4ADD(acc, v1); F4ADD(acc, v2); F4ADD(acc, v3);
    }
    for (; e < end; e++) {
        float4 v = x[(size_t)d_csrsrc[e] * 64 + lane];
        F4ADD(acc, v);
    }
    out[(size_t)n * 64 + lane] = acc;
}

__global__ void __launch_bounds__(128)
gin512_kernel(const float4* __restrict__ x, float4* __restrict__ out)
{
    gin512_body(x, out, blockIdx.x);
}

__global__ void __launch_bounds__(128)
gin_l0_kernel(const float4* __restrict__ x512, float4* __restrict__ out512,
              const float4* __restrict__ x256, float4* __restrict__ out256)
{
    int bid = blockIdx.x;
    if (bid < 2048) gin512_body(x512, out512, bid);
    else            gin256_body(x256, out256, bid - 2048);
}

__global__ void __launch_bounds__(128)
gin_2x256_kernel(const float4* __restrict__ xA, float4* __restrict__ outA,
                 const float4* __restrict__ xB, float4* __restrict__ outB)
{
    int bid = blockIdx.x;
    if (bid < 1024) gin256_body(xA, outA, bid);
    else            gin256_body(xB, outB, bid - 1024);
}

__global__ void __launch_bounds__(128)
gin256_kernel(const float4* __restrict__ x, float4* __restrict__ out)
{
    gin256_body(x, out, blockIdx.x);
}

// Merged GCN (mean) + gin-softplus (std), 32-wide, blockIdx.y in 0..3
__global__ void __launch_bounds__(128)
gcnstd_kernel(const float4* __restrict__ XW, float4* __restrict__ MEAN,
              const float4* __restrict__ mean_b,
              const float4* __restrict__ STMP, float4* __restrict__ STD,
              const float4* __restrict__ std_b)
{
    int y = blockIdx.y;
    int lane = threadIdx.x & 7;
    int n = blockIdx.x * 16 + (threadIdx.x >> 3);
    int beg = d_rowptr[n], end = d_rowptr[n + 1];
    if (y < 2) {
        const float4* xw = XW + (size_t)y * (SZ_ZD / 4);
        float4* out = MEAN + (size_t)y * (SZ_ZD / 4);
        float4 b = mean_b[y * 8 + lane];
        float4 acc = make_float4(0.f, 0.f, 0.f, 0.f);
        for (int e = beg; e < end; e++) {
            int s = d_csrsrc[e];
            float w = d_dinv[s];
            float4 v = xw[(size_t)s * 8 + lane];
            acc.x += w * v.x; acc.y += w * v.y;
            acc.z += w * v.z; acc.w += w * v.w;
        }
        float dn = d_dinv[n], id = 1.f / d_degf[n];
        float4 xn = xw[(size_t)n * 8 + lane];
        out[(size_t)n * 8 + lane] = make_float4(
            dn * acc.x + id * xn.x + b.x, dn * acc.y + id * xn.y + b.y,
            dn * acc.z + id * xn.z + b.z, dn * acc.w + id * xn.w + b.w);
    } else {
        int zz = y - 2;
        const float4* tmp = STMP + (size_t)zz * (SZ_ZD / 4);
        float4* out = STD + (size_t)zz * (SZ_ZD / 4);
        float4 b = std_b[zz * 8 + lane];
        float4 acc = tmp[(size_t)n * 8 + lane];
        int e = beg;
        for (; e + 4 <= end; e += 4) {
            int s0 = d_csrsrc[e],     s1 = d_csrsrc[e + 1];
            int s2 = d_csrsrc[e + 2], s3 = d_csrsrc[e + 3];
            float4 v0 = tmp[(size_t)s0 * 8 + lane];
            float4 v1 = tmp[(size_t)s1 * 8 + lane];
            float4 v2 = tmp[(size_t)s2 * 8 + lane];
            float4 v3 = tmp[(size_t)s3 * 8 + lane];
            F4ADD(acc, v0); F4ADD(acc, v1); F4ADD(acc, v2); F4ADD(acc, v3);
        }
        for (; e < end; e++) {
            float4 v = tmp[(size_t)d_csrsrc[e] * 8 + lane];
            F4ADD(acc, v);
        }
        out[(size_t)n * 8 + lane] = make_float4(
            softplusf(acc.x + b.x), softplusf(acc.y + b.y),
            softplusf(acc.z + b.z), softplusf(acc.w + b.w));
    }
}

// ---------------------------------------------------------------------------
// Init
// ---------------------------------------------------------------------------
__global__ void init_kernel() {
    size_t i = (size_t)blockIdx.x * blockDim.x + threadIdx.x;
    if (i < SZ_2HD)    g_f[O_CAT + i] = 0.f;
    if (i < 2 * SZ_HD) g_f[O_H + i] = 0.f;
    if (i < 6) d_acc[i] = 0.0;
}

// ---------------------------------------------------------------------------
// KLD term
// ---------------------------------------------------------------------------
__device__ __forceinline__ float kterm(float m1, float s1, float m2, float s2) {
    float a = s1 + 1e-10f, b = s2 + 1e-10f;
    float dm = m1 - m2;
    return 2.f * (logf(b) - logf(a)) + (a * a + dm * dm) / (b * b) - 1.f;
}

// ---------------------------------------------------------------------------
// Decoder + BCE partial sums + KLD, merged (blocks 0..1023 dec, 1024..1279 kld)
// ---------------------------------------------------------------------------
__global__ void __launch_bounds__(256)
dec_kld_kernel(const float* __restrict__ zs, const float* __restrict__ zd,
               const float* __restrict__ adj, float* __restrict__ dec,
               const float* __restrict__ ms, const float* __restrict__ ss,
               const float* __restrict__ pm, const float* __restrict__ ps,
               const float* __restrict__ md, const float* __restrict__ sd,
               const float* __restrict__ pmd, const float* __restrict__ psd)
{
    int tid = threadIdx.x;
    if (blockIdx.x >= 1024) {
        int i = (blockIdx.x - 1024) * 256 + tid;   // exactly Nn*ZD = 65536
        float v = kterm(ms[i], ss[i], pm[i], ps[i]) +
                  kterm(md[i], sd[i], pmd[i], psd[i]);
        block_add(&d_acc[3], v);
        return;
    }
    __shared__ float SsT[32][66];
    __shared__ float SdT[32][66];
    int bi = (blockIdx.x >> 5) * 64, bj = (blockIdx.x & 31) * 64;
    for (int i = tid; i < 64 * 32; i += 256) {
        int r = i >> 5, c = i & 31;
        SsT[c][r] = zs[(size_t)(bi + r) * 32 + c];
        SdT[c][r] = zd[(size_t)(bj + r) * 32 + c];
    }
    __syncthreads();
    int tx = tid % 16, ty = tid / 16;
    u64 acc[2][4] = {};
    #pragma unroll
    for (int k = 0; k < 32; k++) {
        const u64* Ap = (const u64*)&SsT[k][ty * 4];
        u64 a0 = Ap[0], a1 = Ap[1];
        const float* bp = &SdT[k][tx * 4];
        u64 b0 = pack2(bp[0], bp[0]), b1 = pack2(bp[1], bp[1]);
        u64 b2 = pack2(bp[2], bp[2]), b3 = pack2(bp[3], bp[3]);
        ffma2(acc[0][0], a0, b0); ffma2(acc[0][1], a0, b1);
        ffma2(acc[0][2], a0, b2); ffma2(acc[0][3], a0, b3);
        ffma2(acc[1][0], a1, b0); ffma2(acc[1][1], a1, b1);
        ffma2(acc[1][2], a1, b2); ffma2(acc[1][3], a1, b3);
    }
    float cr[4][4];
    #pragma unroll
    for (int i2 = 0; i2 < 2; i2++)
        #pragma unroll
        for (int j = 0; j < 4; j++) {
            float2 p = unpack2(acc[i2][j]);
            cr[2 * i2][j] = p.x; cr[2 * i2 + 1][j] = p.y;
        }
    float sa = 0.f, s1 = 0.f, s2 = 0.f;
    #pragma unroll
    for (int i = 0; i < 4; i++) {
        int r = bi + ty * 4 + i;
        #pragma unroll
        for (int j = 0; j < 4; j++) {
            int c = bj + tx * 4 + j;
            float d = cr[i][j];
            dec[(size_t)r * Nn + c] = d;
            float a = adj[(size_t)r * Nn + c];
            float lg = log1pf(expf(-fabsf(d)));
            float lsp = fminf(d, 0.f) - lg;
            float lsn = fminf(-d, 0.f) - lg;
            sa += a; s1 += a * lsp; s2 += (1.f - a) * lsn;
        }
    }
    block_add(&d_acc[0], sa);
    block_add(&d_acc[1], s1);
    block_add(&d_acc[2], s2);
}

__global__ void finalize_kernel(float* __restrict__ out) {
    double ssum = d_acc[0], S1 = d_acc[1], S2 = d_acc[2], K = d_acc[3];
    double nn2 = (double)Nn * (double)Nn;
    double posw = (nn2 - ssum) / ssum;
    double nrm  = nn2 / ((nn2 - ssum) * 2.0);
    double nll  = nrm * ((-posw) * S1 - S2) / nn2;
    double kld  = 0.5 * K / nn2;
    d_acc[4] += kld;
    d_acc[5] += nll;
    out[0] = (float)d_acc[4];
    out[1] = (float)d_acc[5];
    d_acc[0] = 0.0; d_acc[1] = 0.0; d_acc[2] = 0.0; d_acc[3] = 0.0;
}

// ---------------------------------------------------------------------------
// Host orchestration
// ---------------------------------------------------------------------------
extern "C" void kernel_launch(void* const* d_in, const int* /*in_sizes*/, int /*n_in*/,
                              void* d_out, int /*out_size*/)
{
    const float* x       = (const float*)d_in[0];
    const int*   ei      = (const int*)  d_in[1];
    const float* adj     = (const float*)d_in[2];
    const float* eps_s   = (const float*)d_in[3];
    const float* eps_d   = (const float*)d_in[4];
    const float* phi_x_w = (const float*)d_in[5];
    const float* phi_z_w = (const float*)d_in[6];
    const float* gxw0    = (const float*)d_in[7];   // [3,512,256]
    const float* gxw1    = (const float*)d_in[8];   // [3,256,256]
    const float* ghw     = (const float*)d_in[9];   // [2,3,256,256]
    const float* enc_w   = (const float*)d_in[10];  // [2,512,256]
    const float* enc_b   = (const float*)d_in[11];
    const float* mean_w  = (const float*)d_in[12];  // [2,256,32]
    const float* mean_b  = (const float*)d_in[13];
    const float* std_w   = (const float*)d_in[14];
    const float* std_b   = (const float*)d_in[15];
    const float* pri_w   = (const float*)d_in[16];  // [2,256,256]
    const float* pri_b   = (const float*)d_in[17];
    const float* pri_mw  = (const float*)d_in[18];
    const float* pri_mb  = (const float*)d_in[19];
    const float* pri_sw  = (const float*)d_in[20];
    const float* pri_sb  = (const float*)d_in[21];
    float* out = (float*)d_out;
    float* dec_out = out + 2;  // [T, N, N]

    float* F = nullptr;
    cudaGetSymbolAddress((void**)&F, g_f);

    float* CAT    = F + O_CAT;
    float* CATP   = F + O_CATP;
    float* ENC_S  = F + O_ENC_S;
    float* XW_S   = F + O_XW_S;
    float* MEAN_S = F + O_MEAN_S;
    float* MEAN_D = F + O_MEAN_D;
    float* STMP_S = F + O_STMP_S;
    float* STD_S  = F + O_STD_S;
    float* STD_D  = F + O_STD_D;
    float* PRI_S  = F + O_PRI_S;
    float* PM_S   = F + O_PM_S;
    float* PS_S   = F + O_PS_S;
    float* PM_D   = F + O_PM_D;
    float* PS_D   = F + O_PS_D;
    float* Z_S    = F + O_Z_S;
    float* Z_D    = F + O_Z_D;
    float* GPRE   = F + O_GPRE;
    float* HPRE   = F + O_HPRE;
    float* XPRE1  = F + O_XPRE1;
    float* TZ     = F + O_TZ;
    float* TH     = F + O_TH;
    float* RH     = F + O_RH;
    float* RHP    = F + O_RHP;

    init_kernel<<<(SZ_2HD + 255) / 256, 256>>>();

    for (int t = 0; t < Tt; t++) {
        const float* x_t   = x + (size_t)t * Nn * XD;
        const int*   src_t = ei + (size_t)t * 2 * Ee;
        const int*   dst_t = src_t + Ee;
        const float* adj_t = adj + (size_t)t * Nn * Nn;
        const float* es_t  = eps_s + (size_t)t * SZ_ZD;
        const float* ed_t  = eps_d + (size_t)t * SZ_ZD;
        float* Hc = F + O_H + (size_t)(t & 1) * 2 * SZ_HD;
        float* Hn = F + O_H + (size_t)((t + 1) & 1) * 2 * SZ_HD;
        float* hlast = Hc + SZ_HD;
        float* dec_t = dec_out + (size_t)t * Nn * Nn;

        // --- CSR (one launch) ---
        csr_kernel<<<1, 1024>>>(src_t, dst_t);

        // --- phi_x into CAT[:,0:256]; right half holds h_last from prev step ---
        sgemm64<1><<<dim3(4, 32, 1), 128>>>(x_t, phi_x_w, nullptr, CAT,
                                            XD, XD, 256, 512, 0, 0, 0, 0);

        // --- cat_pre = gin(cat) ---
        gin512_kernel<<<2048, 128>>>((const float4*)CAT, (float4*)CATP);

        // --- encoders + priors, grouped (z=4) ---
        encpri_kernel<<<dim3(4, 32, 4), 128>>>(CATP, hlast, enc_w, enc_b,
                                               pri_w, pri_b, ENC_S, PRI_S);

        // --- all eight ZD=32 GEMMs, grouped ---
        g32_kernel<<<dim3(1, 32, 8), 128>>>(ENC_S, PRI_S, mean_w, std_w,
                                            pri_mw, pri_mb, pri_sw, pri_sb,
                                            XW_S, STMP_S, PM_S);

        // --- GCN(mean) + gin-softplus(std), grouped (y=4) ---
        gcnstd_kernel<<<dim3(Nn / 16, 4), 128>>>(
            (const float4*)XW_S, (float4*)MEAN_S, (const float4*)mean_b,
            (const float4*)STMP_S, (float4*)STD_S, (const float4*)std_b);

        // --- phi_z with inline reparameterization -> CAT[:,256:512]; Z persisted ---
        phi_z_kernel<<<dim3(4, 32), 128>>>(
            (const float4*)MEAN_S, (const float4*)STD_S, (const float4*)es_t,
            (const float4*)MEAN_D, (const float4*)STD_D, (const float4*)ed_t,
            phi_z_w, CAT + 256, (float4*)Z_S, (float4*)Z_D);

        // --- decoder + BCE + KLD in one launch; then finalize ---
        dec_kld_kernel<<<1280, 256>>>(Z_S, Z_D, adj_t, dec_t,
                                      MEAN_S, STD_S, PM_S, PS_S,
                                      MEAN_D, STD_D, PM_D, PS_D);
        finalize_kernel<<<1, 1>>>(out);

        // --- graph-GRU, 2 layers ---
        for (int l = 0; l < 2; l++) {
            const float* xi  = (l == 0) ? CAT : Hn;
            float* xpre      = (l == 0) ? GPRE : XPRE1;
            int Kx           = (l == 0) ? 512 : 256;
            const float* xw  = (l == 0) ? gxw0 : gxw1;
            const float* hw  = ghw + (size_t)l * 3 * 256 * 256;
            float* h_l       = Hc + (size_t)l * SZ_HD;
            float* h_out     = Hn + (size_t)l * SZ_HD;
            float* out2      = (l == 1) ? (CAT + 256) : nullptr;

            if (l == 0)
                gin_l0_kernel<<<3072, 128>>>((const float4*)xi, (float4*)xpre,
                                             (const float4*)h_l, (float4*)HPRE);
            else
                gin_2x256_kernel<<<2048, 128>>>((const float4*)xi, (float4*)xpre,
                                                (const float4*)h_l, (float4*)HPRE);

            // all three gates in one launch (virtual K-concat for z,r)
            gru_gates_kernel<<<dim3(4, 32, 3), 128>>>(xpre, HPRE, xw, hw,
                                                      h_l, TZ, RH, TH, Kx);
            // candidate: gin(RH), then fused tanh + blend
            gin256_kernel<<<1024, 128>>>((const float4*)RH, (float4*)RHP);
            sgemm64_cand<<<dim3(4, 32), 128>>>(RHP, hw + 2 * 256 * 256,
                                               TH, TZ, h_l, h_out, out2, 256, 256);
        }
    }
}